// round 13
// baseline (speedup 1.0000x reference)
#include <cuda_runtime.h>
#include <cuda_bf16.h>
#include <cstdint>

// DecoderBlock: self-MHA (causal) -> cross-MHA (no mask).
// B=4, S=1024, D=1024, H=16, DK=64.
// All matmuls mma.sync bf16 hi/lo split (fp32 accum).
// R13: GEMM warp tile 64x64, 8 warps, CTA 128x256 (LDSM bytes/MMA cut 2.67x,
//      smem 1024cyc < MMA 1536cyc per k-tile), R10 3-buffer pipeline, 1 CTA/SM
//      but 8 warps/SM (the density attention proves sufficient).

#define SEQ    1024
#define DMODEL 1024
#define NHEAD  16
#define HDIM   64
#define BATCH  4
#define MTOT   (BATCH * SEQ)   // 4096

// ---------------- scratch ----------------
__device__ __nv_bfloat16 g_qh[(size_t)MTOT * DMODEL];
__device__ __nv_bfloat16 g_ql[(size_t)MTOT * DMODEL];
__device__ __nv_bfloat16 g_kh[(size_t)MTOT * DMODEL];
__device__ __nv_bfloat16 g_kl[(size_t)MTOT * DMODEL];
__device__ __nv_bfloat16 g_vh[(size_t)MTOT * DMODEL];
__device__ __nv_bfloat16 g_vl[(size_t)MTOT * DMODEL];
__device__ __nv_bfloat16 g_ah[(size_t)MTOT * DMODEL];
__device__ __nv_bfloat16 g_al[(size_t)MTOT * DMODEL];
__device__ __nv_bfloat16 g_eh[(size_t)MTOT * DMODEL];
__device__ __nv_bfloat16 g_el[(size_t)MTOT * DMODEL];
__device__ __nv_bfloat16 g_w6h[6 * (size_t)DMODEL * DMODEL];
__device__ __nv_bfloat16 g_w6l[6 * (size_t)DMODEL * DMODEL];

// ================= PTX helpers =================
__device__ __forceinline__ uint32_t smem_u32(const void* p) {
    uint32_t a;
    asm("{ .reg .u64 t; cvta.to.shared.u64 t, %1; cvt.u32.u64 %0, t; }" : "=r"(a) : "l"(p));
    return a;
}
#define CP_ASYNC16(dst, src) asm volatile("cp.async.cg.shared.global [%0], [%1], 16;" :: "r"(dst), "l"(src))
#define CP_COMMIT()  asm volatile("cp.async.commit_group;" ::: "memory")
#define CP_WAIT1()   asm volatile("cp.async.wait_group 1;" ::: "memory")
#define CP_WAIT0()   asm volatile("cp.async.wait_group 0;" ::: "memory")

#define LDSM_X4(r0, r1, r2, r3, addr) \
    asm volatile("ldmatrix.sync.aligned.m8n8.x4.shared.b16 {%0,%1,%2,%3}, [%4];" \
                 : "=r"(r0), "=r"(r1), "=r"(r2), "=r"(r3) : "r"(addr))
#define LDSM_X4_T(r0, r1, r2, r3, addr) \
    asm volatile("ldmatrix.sync.aligned.m8n8.x4.trans.shared.b16 {%0,%1,%2,%3}, [%4];" \
                 : "=r"(r0), "=r"(r1), "=r"(r2), "=r"(r3) : "r"(addr))

#define MMA_BF16(c, a, b0v, b1v) \
    asm volatile("mma.sync.aligned.m16n8k16.row.col.f32.bf16.bf16.f32 " \
                 "{%0,%1,%2,%3}, {%4,%5,%6,%7}, {%8,%9}, {%0,%1,%2,%3};" \
                 : "+f"((c)[0]), "+f"((c)[1]), "+f"((c)[2]), "+f"((c)[3]) \
                 : "r"((a)[0]), "r"((a)[1]), "r"((a)[2]), "r"((a)[3]), \
                   "r"(b0v), "r"(b1v))

__device__ __forceinline__ void pack_split(float a, float b, uint32_t& h, uint32_t& l) {
    __nv_bfloat16 ha = __float2bfloat16(a), hb = __float2bfloat16(b);
    float ra = a - __bfloat162float(ha), rb = b - __bfloat162float(hb);
    __nv_bfloat162 hh = __halves2bfloat162(ha, hb);
    __nv_bfloat162 ll = __halves2bfloat162(__float2bfloat16(ra), __float2bfloat16(rb));
    h = *reinterpret_cast<uint32_t*>(&hh);
    l = *reinterpret_cast<uint32_t*>(&ll);
}

// ================= batched split fp32 -> bf16 hi/lo =================
struct SplitBatch {
    const float* src[2];
    __nv_bfloat16* hi[2];
    __nv_bfloat16* lo[2];
};

__global__ __launch_bounds__(256) void split_multi(SplitBatch S) {
    const float* x = S.src[blockIdx.y];
    __nv_bfloat16* hi = S.hi[blockIdx.y];
    __nv_bfloat16* lo = S.lo[blockIdx.y];
    size_t i = ((size_t)blockIdx.x * 256 + threadIdx.x) * 4;
    float4 v = *(const float4*)(x + i);
    uint32_t h0, l0, h1, l1;
    pack_split(v.x, v.y, h0, l0);
    pack_split(v.z, v.w, h1, l1);
    *(uint32_t*)(hi + i)     = h0; *(uint32_t*)(hi + i + 2) = h1;
    *(uint32_t*)(lo + i)     = l0; *(uint32_t*)(lo + i + 2) = l1;
}

// ================= fused-split mma.sync GEMM (QKV in one grid) =================
// C = A * B^T (4096x1024x1024) per z; 3 passes: Ah*Bh + Ah*Bl + Al*Bh.
// CTA 128x256, 256 thr = 8 warps @64x64. 3-buffer cp.async (R10 pipeline),
// XOR-swizzled 64B rows, 144KB smem -> 1 CTA/SM, 8 warps/SM.
#define BM 128
#define BN 256
#define GT 256
#define TILE_A 8192                    // 128 rows * 64B
#define TILE_BB 16384                  // 256 rows * 64B
#define OFF_AH 0
#define OFF_AL TILE_A
#define OFF_BH (2 * TILE_A)
#define OFF_BL (2 * TILE_A + TILE_BB)
#define STAGE_B (2 * TILE_A + 2 * TILE_BB)   // 49152
#define NK 32
#define GEMM_SMEM (3 * STAGE_B)        // 147456

struct GemmTriple {
    const __nv_bfloat16* Ah[3];
    const __nv_bfloat16* Al[3];
    const __nv_bfloat16* Bh[3];
    const __nv_bfloat16* Bl[3];
    __nv_bfloat16* Ch[3];
    __nv_bfloat16* Cl[3];
};

__device__ __forceinline__ void issue_stage(uint32_t sbase,
                                            const __nv_bfloat16* Ahp, const __nv_bfloat16* Alp,
                                            const __nv_bfloat16* Bhp, const __nv_bfloat16* Blp,
                                            int kt, int tid) {
    // A tiles: 512 chunks each / 256 thr = 2 per thread per tile
#pragma unroll
    for (int i = 0; i < 2; i++) {
        const int idx = tid + i * GT;
        const int r = idx >> 2, c = idx & 3;
        const size_t goff = (size_t)r * 1024 + (size_t)kt * 32 + c * 8;
        const uint32_t soff = (uint32_t)(r * 64 + ((c ^ ((r >> 1) & 3)) * 16));
        CP_ASYNC16(sbase + OFF_AH + soff, (const char*)(Ahp + goff));
        CP_ASYNC16(sbase + OFF_AL + soff, (const char*)(Alp + goff));
    }
    // B tiles: 1024 chunks each / 256 thr = 4 per thread per tile
#pragma unroll
    for (int i = 0; i < 4; i++) {
        const int idx = tid + i * GT;
        const int r = idx >> 2, c = idx & 3;
        const size_t goff = (size_t)r * 1024 + (size_t)kt * 32 + c * 8;
        const uint32_t soff = (uint32_t)(r * 64 + ((c ^ ((r >> 1) & 3)) * 16));
        CP_ASYNC16(sbase + OFF_BH + soff, (const char*)(Bhp + goff));
        CP_ASYNC16(sbase + OFF_BL + soff, (const char*)(Blp + goff));
    }
}

__global__ __launch_bounds__(GT)
void gemm_qkv(GemmTriple P) {
    extern __shared__ char smc[];
    uint32_t sb = smem_u32(smc);
    const int tid = threadIdx.x;
    const int wid = tid >> 5, lane = tid & 31;
    const int z = blockIdx.z;
    const int m0 = blockIdx.y * BM;
    const int n0 = blockIdx.x * BN;
    const int wm = (wid & 1) * 64;      // 2 m-slots
    const int wn = (wid >> 1) * 64;     // 4 n-slots

    const __nv_bfloat16* Ahp = P.Ah[z] + (size_t)m0 * 1024;
    const __nv_bfloat16* Alp = P.Al[z] + (size_t)m0 * 1024;
    const __nv_bfloat16* Bhp = P.Bh[z] + (size_t)n0 * 1024;
    const __nv_bfloat16* Blp = P.Bl[z] + (size_t)n0 * 1024;

    const int lrow = (lane & 7) + ((lane >> 3) & 1) * 8;
    const int hi5 = (lane >> 4) & 1;   // k-half chunk bit

    float acc[4][8][4];
#pragma unroll
    for (int mt = 0; mt < 4; mt++)
#pragma unroll
        for (int nt = 0; nt < 8; nt++)
#pragma unroll
            for (int q = 0; q < 4; q++) acc[mt][nt][q] = 0.f;

    issue_stage(sb + 0 * STAGE_B, Ahp, Alp, Bhp, Blp, 0, tid);
    CP_COMMIT();
    issue_stage(sb + 1 * STAGE_B, Ahp, Alp, Bhp, Blp, 1, tid);
    CP_COMMIT();

    for (int kt = 0; kt < NK; kt++) {
        CP_WAIT1();            // stage kt landed
        __syncthreads();       // buffer (kt+2)%3 fully consumed (computed in kt-1)
        if (kt + 2 < NK)
            issue_stage(sb + ((kt + 2) % 3) * STAGE_B, Ahp, Alp, Bhp, Blp, kt + 2, tid);
        CP_COMMIT();

        const uint32_t stb = sb + (kt % 3) * STAGE_B;
#pragma unroll
        for (int ks = 0; ks < 2; ks++) {
            uint32_t ah[4][4], al[4][4];
#pragma unroll
            for (int mt = 0; mt < 4; mt++) {
                const int row = wm + mt * 16 + lrow;
                const uint32_t ro = (uint32_t)(row * 64 +
                    (((ks * 2 + hi5) ^ ((row >> 1) & 3)) * 16));
                LDSM_X4(ah[mt][0], ah[mt][1], ah[mt][2], ah[mt][3], stb + OFF_AH + ro);
                LDSM_X4(al[mt][0], al[mt][1], al[mt][2], al[mt][3], stb + OFF_AL + ro);
            }
#pragma unroll
            for (int g = 0; g < 4; g++) {   // four 16-col B groups -> nt = 2g, 2g+1
                const int row = wn + g * 16 + lrow;
                const uint32_t ro = (uint32_t)(row * 64 +
                    (((ks * 2 + hi5) ^ ((row >> 1) & 3)) * 16));
                uint32_t h0, h1, h2, h3, l0, l1, l2, l3;
                LDSM_X4(h0, h1, h2, h3, stb + OFF_BH + ro);
                LDSM_X4(l0, l1, l2, l3, stb + OFF_BL + ro);
                // pass 1: Ah*Bh (8 independent MMAs)
#pragma unroll
                for (int mt = 0; mt < 4; mt++) {
                    MMA_BF16(acc[mt][2 * g + 0], ah[mt], h0, h2);
                    MMA_BF16(acc[mt][2 * g + 1], ah[mt], h1, h3);
                }
                // pass 2: Ah*Bl
#pragma unroll
                for (int mt = 0; mt < 4; mt++) {
                    MMA_BF16(acc[mt][2 * g + 0], ah[mt], l0, l2);
                    MMA_BF16(acc[mt][2 * g + 1], ah[mt], l1, l3);
                }
                // pass 3: Al*Bh
#pragma unroll
                for (int mt = 0; mt < 4; mt++) {
                    MMA_BF16(acc[mt][2 * g + 0], al[mt], h0, h2);
                    MMA_BF16(acc[mt][2 * g + 1], al[mt], h1, h3);
                }
            }
        }
    }

    __nv_bfloat16* Ch = P.Ch[z];
    __nv_bfloat16* Cl = P.Cl[z];
#pragma unroll
    for (int mt = 0; mt < 4; mt++) {
#pragma unroll
        for (int nt = 0; nt < 8; nt++) {
            int row = m0 + wm + mt * 16 + (lane >> 2);
            int col = n0 + wn + nt * 8 + (lane & 3) * 2;
            uint32_t h01, l01, h23, l23;
            pack_split(acc[mt][nt][0], acc[mt][nt][1], h01, l01);
            pack_split(acc[mt][nt][2], acc[mt][nt][3], h23, l23);
            *(uint32_t*)(Ch + (size_t)row * 1024 + col) = h01;
            *(uint32_t*)(Cl + (size_t)row * 1024 + col) = l01;
            *(uint32_t*)(Ch + (size_t)(row + 8) * 1024 + col) = h23;
            *(uint32_t*)(Cl + (size_t)(row + 8) * 1024 + col) = l23;
        }
    }
}

// ================= tensor-core flash attention (bf16 split, fp32 softmax) =================
#define APITCH 72
#define ATILE_B2 (64 * APITCH * 2)    // 9216
#define AQ_H 0
#define AQ_L ATILE_B2
#define AST(s, t) (2 * ATILE_B2 + (s) * (4 * ATILE_B2) + (t) * ATILE_B2)
#define ATTN_SMEM (2 * ATILE_B2 + 2 * 4 * ATILE_B2)   // 92160

__device__ __forceinline__ void attn_load_tile(uint32_t dst, const __nv_bfloat16* src, int tid) {
#pragma unroll
    for (int i = 0; i < 4; i++) {
        int idx = tid + i * 128;
        int r = idx >> 3, c = idx & 7;
        CP_ASYNC16(dst + (uint32_t)(r * 144 + c * 16),
                   (const char*)(src + (size_t)r * 1024 + c * 8));
    }
}

__global__ __launch_bounds__(128, 2)
void attn_mma(const __nv_bfloat16* __restrict__ Qh, const __nv_bfloat16* __restrict__ Ql,
              const __nv_bfloat16* __restrict__ Kh, const __nv_bfloat16* __restrict__ Kl,
              const __nv_bfloat16* __restrict__ Vh, const __nv_bfloat16* __restrict__ Vl,
              float* __restrict__ Of,
              __nv_bfloat16* __restrict__ Oh, __nv_bfloat16* __restrict__ Ol,
              int causal) {
    extern __shared__ char smc[];
    uint32_t sb = smem_u32(smc);
    const int tid = threadIdx.x;
    const int wid = tid >> 5, lane = tid & 31;
    const int q0 = blockIdx.x * 64;
    const int h = blockIdx.y, b = blockIdx.z;
    const size_t rowbase = (size_t)(b * SEQ);
    const int colbase = h * HDIM;

    const int lrow = (lane & 7) + ((lane >> 3) & 1) * 8;
    const int lkof = ((lane >> 4) & 1) * 8;
    const int vrow_l = (lane & 7) + ((lane >> 4) & 1) * 8;
    const int vcol_l = ((lane >> 3) & 1) * 8;

    attn_load_tile(sb + AQ_H, Qh + (rowbase + q0) * 1024 + colbase, tid);
    attn_load_tile(sb + AQ_L, Ql + (rowbase + q0) * 1024 + colbase, tid);
    attn_load_tile(sb + AST(0, 0), Kh + rowbase * 1024 + colbase, tid);
    attn_load_tile(sb + AST(0, 1), Kl + rowbase * 1024 + colbase, tid);
    attn_load_tile(sb + AST(0, 2), Vh + rowbase * 1024 + colbase, tid);
    attn_load_tile(sb + AST(0, 3), Vl + rowbase * 1024 + colbase, tid);
    CP_COMMIT();

    const int njt = causal ? (blockIdx.x + 1) : (SEQ / 64);

    uint32_t qhf[4][4], qlf[4][4];
    float o[8][4];
#pragma unroll
    for (int nt = 0; nt < 8; nt++)
#pragma unroll
        for (int q = 0; q < 4; q++) o[nt][q] = 0.f;
    float m_[2] = {-1e30f, -1e30f}, l_[2] = {0.f, 0.f};

    for (int j = 0; j < njt; j++) {
        CP_WAIT0();
        __syncthreads();
        if (j + 1 < njt) {
            const size_t kb = (rowbase + (size_t)(j + 1) * 64) * 1024 + colbase;
            const int s = (j + 1) & 1;
            attn_load_tile(sb + AST(s, 0), Kh + kb, tid);
            attn_load_tile(sb + AST(s, 1), Kl + kb, tid);
            attn_load_tile(sb + AST(s, 2), Vh + kb, tid);
            attn_load_tile(sb + AST(s, 3), Vl + kb, tid);
            CP_COMMIT();
        }
        if (j == 0) {
#pragma unroll
            for (int kt = 0; kt < 4; kt++) {
                uint32_t ro = (uint32_t)((wid * 16 + lrow) * 144 + (kt * 16 + lkof) * 2);
                LDSM_X4(qhf[kt][0], qhf[kt][1], qhf[kt][2], qhf[kt][3], sb + AQ_H + ro);
                LDSM_X4(qlf[kt][0], qlf[kt][1], qlf[kt][2], qlf[kt][3], sb + AQ_L + ro);
            }
        }

        const uint32_t khb = sb + AST(j & 1, 0);
        const uint32_t klb = sb + AST(j & 1, 1);
        const uint32_t vhb = sb + AST(j & 1, 2);
        const uint32_t vlb = sb + AST(j & 1, 3);

        float s[8][4];
#pragma unroll
        for (int nt = 0; nt < 8; nt++)
#pragma unroll
            for (int q = 0; q < 4; q++) s[nt][q] = 0.f;
#pragma unroll
        for (int kt = 0; kt < 4; kt++) {
            uint32_t bh[8][2], bl[8][2];
#pragma unroll
            for (int g = 0; g < 4; g++) {
                uint32_t ro = (uint32_t)((g * 16 + lrow) * 144 + (kt * 16 + lkof) * 2);
                uint32_t r0, r1, r2, r3;
                LDSM_X4(r0, r1, r2, r3, khb + ro);
                bh[2 * g + 0][0] = r0; bh[2 * g + 0][1] = r2;
                bh[2 * g + 1][0] = r1; bh[2 * g + 1][1] = r3;
                LDSM_X4(r0, r1, r2, r3, klb + ro);
                bl[2 * g + 0][0] = r0; bl[2 * g + 0][1] = r2;
                bl[2 * g + 1][0] = r1; bl[2 * g + 1][1] = r3;
            }
#pragma unroll
            for (int nt = 0; nt < 8; nt++)
                MMA_BF16(s[nt], qhf[kt], bh[nt][0], bh[nt][1]);
#pragma unroll
            for (int nt = 0; nt < 8; nt++)
                MMA_BF16(s[nt], qhf[kt], bl[nt][0], bl[nt][1]);
#pragma unroll
            for (int nt = 0; nt < 8; nt++)
                MMA_BF16(s[nt], qlf[kt], bh[nt][0], bh[nt][1]);
        }

#pragma unroll
        for (int nt = 0; nt < 8; nt++)
#pragma unroll
            for (int q = 0; q < 4; q++) s[nt][q] *= 0.125f;
        if (causal && j == njt - 1) {
            const int r0l = wid * 16 + (lane >> 2), r1l = r0l + 8;
#pragma unroll
            for (int nt = 0; nt < 8; nt++) {
                const int c0 = nt * 8 + (lane & 3) * 2;
                if (c0 > r0l)     s[nt][0] = -1e9f;
                if (c0 + 1 > r0l) s[nt][1] = -1e9f;
                if (c0 > r1l)     s[nt][2] = -1e9f;
                if (c0 + 1 > r1l) s[nt][3] = -1e9f;
            }
        }

        float mx0 = -1e30f, mx1 = -1e30f;
#pragma unroll
        for (int nt = 0; nt < 8; nt++) {
            mx0 = fmaxf(mx0, fmaxf(s[nt][0], s[nt][1]));
            mx1 = fmaxf(mx1, fmaxf(s[nt][2], s[nt][3]));
        }
        mx0 = fmaxf(mx0, __shfl_xor_sync(0xffffffffu, mx0, 1));
        mx0 = fmaxf(mx0, __shfl_xor_sync(0xffffffffu, mx0, 2));
        mx1 = fmaxf(mx1, __shfl_xor_sync(0xffffffffu, mx1, 1));
        mx1 = fmaxf(mx1, __shfl_xor_sync(0xffffffffu, mx1, 2));
        const float mn0 = fmaxf(m_[0], mx0), mn1 = fmaxf(m_[1], mx1);
        const float f0 = __expf(m_[0] - mn0), f1 = __expf(m_[1] - mn1);
        m_[0] = mn0; m_[1] = mn1;
        float rs0 = 0.f, rs1 = 0.f;
#pragma unroll
        for (int nt = 0; nt < 8; nt++) {
            s[nt][0] = __expf(s[nt][0] - mn0);
            s[nt][1] = __expf(s[nt][1] - mn0);
            s[nt][2] = __expf(s[nt][2] - mn1);
            s[nt][3] = __expf(s[nt][3] - mn1);
            rs0 += s[nt][0] + s[nt][1];
            rs1 += s[nt][2] + s[nt][3];
        }
        rs0 += __shfl_xor_sync(0xffffffffu, rs0, 1);
        rs0 += __shfl_xor_sync(0xffffffffu, rs0, 2);
        rs1 += __shfl_xor_sync(0xffffffffu, rs1, 1);
        rs1 += __shfl_xor_sync(0xffffffffu, rs1, 2);
        l_[0] = l_[0] * f0 + rs0;
        l_[1] = l_[1] * f1 + rs1;
#pragma unroll
        for (int nt = 0; nt < 8; nt++) {
            o[nt][0] *= f0; o[nt][1] *= f0; o[nt][2] *= f1; o[nt][3] *= f1;
        }

        uint32_t ph[4][4], pl[4][4];
#pragma unroll
        for (int kt = 0; kt < 4; kt++) {
            pack_split(s[2 * kt][0],     s[2 * kt][1],     ph[kt][0], pl[kt][0]);
            pack_split(s[2 * kt][2],     s[2 * kt][3],     ph[kt][1], pl[kt][1]);
            pack_split(s[2 * kt + 1][0], s[2 * kt + 1][1], ph[kt][2], pl[kt][2]);
            pack_split(s[2 * kt + 1][2], s[2 * kt + 1][3], ph[kt][3], pl[kt][3]);
        }

#pragma unroll
        for (int kt = 0; kt < 4; kt++) {
            const uint32_t vro = (uint32_t)((kt * 16 + vrow_l) * 144);
            uint32_t bh[8][2], bl[8][2];
#pragma unroll
            for (int g = 0; g < 4; g++) {
                uint32_t ro = vro + (uint32_t)((g * 16 + vcol_l) * 2);
                uint32_t r0, r1, r2, r3;
                LDSM_X4_T(r0, r1, r2, r3, vhb + ro);
                bh[2 * g + 0][0] = r0; bh[2 * g + 0][1] = r2;
                bh[2 * g + 1][0] = r1; bh[2 * g + 1][1] = r3;
                LDSM_X4_T(r0, r1, r2, r3, vlb + ro);
                bl[2 * g + 0][0] = r0; bl[2 * g + 0][1] = r2;
                bl[2 * g + 1][0] = r1; bl[2 * g + 1][1] = r3;
            }
#pragma unroll
            for (int nt = 0; nt < 8; nt++)
                MMA_BF16(o[nt], ph[kt], bh[nt][0], bh[nt][1]);
#pragma unroll
            for (int nt = 0; nt < 8; nt++)
                MMA_BF16(o[nt], ph[kt], bl[nt][0], bl[nt][1]);
#pragma unroll
            for (int nt = 0; nt < 8; nt++)
                MMA_BF16(o[nt], pl[kt], bh[nt][0], bh[nt][1]);
        }
    }

    const float inv0 = 1.f / l_[0], inv1 = 1.f / l_[1];
    const size_t row0 = rowbase + q0 + wid * 16 + (lane >> 2);
    const int col = colbase + (lane & 3) * 2;
    if (Of) {
#pragma unroll
        for (int nt = 0; nt < 8; nt++) {
            *(float2*)(Of + row0 * 1024 + col + nt * 8) =
                make_float2(o[nt][0] * inv0, o[nt][1] * inv0);
            *(float2*)(Of + (row0 + 8) * 1024 + col + nt * 8) =
                make_float2(o[nt][2] * inv1, o[nt][3] * inv1);
        }
    } else {
#pragma unroll
        for (int nt = 0; nt < 8; nt++) {
            uint32_t h01, l01, h23, l23;
            pack_split(o[nt][0] * inv0, o[nt][1] * inv0, h01, l01);
            pack_split(o[nt][2] * inv1, o[nt][3] * inv1, h23, l23);
            *(uint32_t*)(Oh + row0 * 1024 + col + nt * 8) = h01;
            *(uint32_t*)(Ol + row0 * 1024 + col + nt * 8) = l01;
            *(uint32_t*)(Oh + (row0 + 8) * 1024 + col + nt * 8) = h23;
            *(uint32_t*)(Ol + (row0 + 8) * 1024 + col + nt * 8) = l23;
        }
    }
}

// ================= launch =================
extern "C" void kernel_launch(void* const* d_in, const int* in_sizes, int n_in,
                              void* d_out, int out_size) {
    const float* x   = (const float*)d_in[0];
    const float* enc = (const float*)d_in[1];
    const float* w[6] = {(const float*)d_in[4], (const float*)d_in[5],
                         (const float*)d_in[6], (const float*)d_in[7],
                         (const float*)d_in[8], (const float*)d_in[9]};
    float* out = (float*)d_out;

    __nv_bfloat16 *qh, *ql, *kh, *kl, *vh, *vl, *ah, *al, *eh, *el, *wh, *wl;
    cudaGetSymbolAddress((void**)&qh, g_qh);
    cudaGetSymbolAddress((void**)&ql, g_ql);
    cudaGetSymbolAddress((void**)&kh, g_kh);
    cudaGetSymbolAddress((void**)&kl, g_kl);
    cudaGetSymbolAddress((void**)&vh, g_vh);
    cudaGetSymbolAddress((void**)&vl, g_vl);
    cudaGetSymbolAddress((void**)&ah, g_ah);
    cudaGetSymbolAddress((void**)&al, g_al);
    cudaGetSymbolAddress((void**)&eh, g_eh);
    cudaGetSymbolAddress((void**)&el, g_el);
    cudaGetSymbolAddress((void**)&wh, g_w6h);
    cudaGetSymbolAddress((void**)&wl, g_w6l);

    cudaFuncSetAttribute(gemm_qkv, cudaFuncAttributeMaxDynamicSharedMemorySize, GEMM_SMEM);
    cudaFuncSetAttribute(attn_mma, cudaFuncAttributeMaxDynamicSharedMemorySize, ATTN_SMEM);

    const size_t WSZ = (size_t)DMODEL * DMODEL;
    const int actBlocks = (MTOT * DMODEL) / (256 * 4);   // 4096
    const int wBlocks   = (int)(WSZ / (256 * 4));        // 1024
    dim3 gg(DMODEL / BN, MTOT / BM, 3);                  // (4, 32, 3)
    dim3 ga(SEQ / 64, NHEAD, BATCH);                     // (16, 16, 4)

    // 5 split launches so gemm_qkv is launch #6 (ncu -s 5 -c 1 profiles it)
    SplitBatch S1 = {}; S1.src[0] = x;   S1.hi[0] = ah; S1.lo[0] = al;
    split_multi<<<dim3(actBlocks, 1), 256>>>(S1);                        // 1
    SplitBatch S2 = {}; S2.src[0] = enc; S2.hi[0] = eh; S2.lo[0] = el;
    split_multi<<<dim3(actBlocks, 1), 256>>>(S2);                        // 2
    for (int p = 0; p < 3; p++) {                                        // 3,4,5
        SplitBatch Sw = {};
        for (int i = 0; i < 2; i++) {
            int wi = p * 2 + i;
            Sw.src[i] = w[wi]; Sw.hi[i] = wh + wi * WSZ; Sw.lo[i] = wl + wi * WSZ;
        }
        split_multi<<<dim3(wBlocks, 2), 256>>>(Sw);
    }

    // ---- self-attention block ----
    GemmTriple Ps;
    for (int zi = 0; zi < 3; zi++) {
        Ps.Ah[zi] = ah; Ps.Al[zi] = al;
        Ps.Bh[zi] = wh + zi * WSZ; Ps.Bl[zi] = wl + zi * WSZ;
    }
    Ps.Ch[0] = qh; Ps.Cl[0] = ql;
    Ps.Ch[1] = kh; Ps.Cl[1] = kl;
    Ps.Ch[2] = vh; Ps.Cl[2] = vl;
    gemm_qkv<<<gg, GT, GEMM_SMEM>>>(Ps);                                 // 6 (profiled)
    attn_mma<<<ga, 128, ATTN_SMEM>>>(qh, ql, kh, kl, vh, vl, nullptr, ah, al, 1);

    // ---- cross-attention block ----
    GemmTriple Pc;
    Pc.Ah[0] = ah; Pc.Al[0] = al;
    Pc.Ah[1] = eh; Pc.Al[1] = el;
    Pc.Ah[2] = eh; Pc.Al[2] = el;
    for (int zi = 0; zi < 3; zi++) {
        Pc.Bh[zi] = wh + (3 + zi) * WSZ; Pc.Bl[zi] = wl + (3 + zi) * WSZ;
    }
    Pc.Ch[0] = qh; Pc.Cl[0] = ql;
    Pc.Ch[1] = kh; Pc.Cl[1] = kl;
    Pc.Ch[2] = vh; Pc.Cl[2] = vl;
    gemm_qkv<<<gg, GT, GEMM_SMEM>>>(Pc);
    attn_mma<<<ga, 128, ATTN_SMEM>>>(qh, ql, kh, kl, vh, vl, out, nullptr, nullptr, 0);
}

// round 14
// speedup vs baseline: 1.0385x; 1.0385x over previous
#include <cuda_runtime.h>
#include <cuda_bf16.h>
#include <cstdint>

// DecoderBlock: self-MHA (causal) -> cross-MHA (no mask).
// B=4, S=1024, D=1024, H=16, DK=64.
// All matmuls mma.sync bf16 hi/lo split (fp32 accum).
// R14: GEMM mirrors attention's occupancy shape: 128-thr CTA (4 warps @64x64),
//      CTA tile 128x128, 3-stage 96KB -> 2 CTAs/SM, 8 warps/SM, LDSM:MMA=1:6.

#define SEQ    1024
#define DMODEL 1024
#define NHEAD  16
#define HDIM   64
#define BATCH  4
#define MTOT   (BATCH * SEQ)   // 4096

// ---------------- scratch ----------------
__device__ __nv_bfloat16 g_qh[(size_t)MTOT * DMODEL];
__device__ __nv_bfloat16 g_ql[(size_t)MTOT * DMODEL];
__device__ __nv_bfloat16 g_kh[(size_t)MTOT * DMODEL];
__device__ __nv_bfloat16 g_kl[(size_t)MTOT * DMODEL];
__device__ __nv_bfloat16 g_vh[(size_t)MTOT * DMODEL];
__device__ __nv_bfloat16 g_vl[(size_t)MTOT * DMODEL];
__device__ __nv_bfloat16 g_ah[(size_t)MTOT * DMODEL];
__device__ __nv_bfloat16 g_al[(size_t)MTOT * DMODEL];
__device__ __nv_bfloat16 g_eh[(size_t)MTOT * DMODEL];
__device__ __nv_bfloat16 g_el[(size_t)MTOT * DMODEL];
__device__ __nv_bfloat16 g_w6h[6 * (size_t)DMODEL * DMODEL];
__device__ __nv_bfloat16 g_w6l[6 * (size_t)DMODEL * DMODEL];

// ================= PTX helpers =================
__device__ __forceinline__ uint32_t smem_u32(const void* p) {
    uint32_t a;
    asm("{ .reg .u64 t; cvta.to.shared.u64 t, %1; cvt.u32.u64 %0, t; }" : "=r"(a) : "l"(p));
    return a;
}
#define CP_ASYNC16(dst, src) asm volatile("cp.async.cg.shared.global [%0], [%1], 16;" :: "r"(dst), "l"(src))
#define CP_COMMIT()  asm volatile("cp.async.commit_group;" ::: "memory")
#define CP_WAIT1()   asm volatile("cp.async.wait_group 1;" ::: "memory")
#define CP_WAIT0()   asm volatile("cp.async.wait_group 0;" ::: "memory")

#define LDSM_X4(r0, r1, r2, r3, addr) \
    asm volatile("ldmatrix.sync.aligned.m8n8.x4.shared.b16 {%0,%1,%2,%3}, [%4];" \
                 : "=r"(r0), "=r"(r1), "=r"(r2), "=r"(r3) : "r"(addr))
#define LDSM_X4_T(r0, r1, r2, r3, addr) \
    asm volatile("ldmatrix.sync.aligned.m8n8.x4.trans.shared.b16 {%0,%1,%2,%3}, [%4];" \
                 : "=r"(r0), "=r"(r1), "=r"(r2), "=r"(r3) : "r"(addr))

#define MMA_BF16(c, a, b0v, b1v) \
    asm volatile("mma.sync.aligned.m16n8k16.row.col.f32.bf16.bf16.f32 " \
                 "{%0,%1,%2,%3}, {%4,%5,%6,%7}, {%8,%9}, {%0,%1,%2,%3};" \
                 : "+f"((c)[0]), "+f"((c)[1]), "+f"((c)[2]), "+f"((c)[3]) \
                 : "r"((a)[0]), "r"((a)[1]), "r"((a)[2]), "r"((a)[3]), \
                   "r"(b0v), "r"(b1v))

__device__ __forceinline__ void pack_split(float a, float b, uint32_t& h, uint32_t& l) {
    __nv_bfloat16 ha = __float2bfloat16(a), hb = __float2bfloat16(b);
    float ra = a - __bfloat162float(ha), rb = b - __bfloat162float(hb);
    __nv_bfloat162 hh = __halves2bfloat162(ha, hb);
    __nv_bfloat162 ll = __halves2bfloat162(__float2bfloat16(ra), __float2bfloat16(rb));
    h = *reinterpret_cast<uint32_t*>(&hh);
    l = *reinterpret_cast<uint32_t*>(&ll);
}

// ================= batched split fp32 -> bf16 hi/lo =================
struct SplitBatch {
    const float* src[2];
    __nv_bfloat16* hi[2];
    __nv_bfloat16* lo[2];
};

__global__ __launch_bounds__(256) void split_multi(SplitBatch S) {
    const float* x = S.src[blockIdx.y];
    __nv_bfloat16* hi = S.hi[blockIdx.y];
    __nv_bfloat16* lo = S.lo[blockIdx.y];
    size_t i = ((size_t)blockIdx.x * 256 + threadIdx.x) * 4;
    float4 v = *(const float4*)(x + i);
    uint32_t h0, l0, h1, l1;
    pack_split(v.x, v.y, h0, l0);
    pack_split(v.z, v.w, h1, l1);
    *(uint32_t*)(hi + i)     = h0; *(uint32_t*)(hi + i + 2) = h1;
    *(uint32_t*)(lo + i)     = l0; *(uint32_t*)(lo + i + 2) = l1;
}

// ================= fused-split mma.sync GEMM (QKV in one grid) =================
// C = A * B^T (4096x1024x1024) per z; 3 passes: Ah*Bh + Ah*Bl + Al*Bh.
// CTA 128x128, 128 thr = 4 warps @64x64. 3-stage cp.async XOR-swizzled,
// 96KB smem -> 2 CTAs/SM (8 warps/SM), LDSM:MMA = 1:6 like attention.
#define BM 128
#define BN 128
#define GT 128
#define TILE_T 8192                    // 128 rows * 64B per tile
#define OFF_AH 0
#define OFF_AL TILE_T
#define OFF_BH (2 * TILE_T)
#define OFF_BL (3 * TILE_T)
#define STAGE_B (4 * TILE_T)           // 32768
#define NK 32
#define GEMM_SMEM (3 * STAGE_B)        // 98304

struct GemmTriple {
    const __nv_bfloat16* Ah[3];
    const __nv_bfloat16* Al[3];
    const __nv_bfloat16* Bh[3];
    const __nv_bfloat16* Bl[3];
    __nv_bfloat16* Ch[3];
    __nv_bfloat16* Cl[3];
};

__device__ __forceinline__ void issue_stage(uint32_t sbase,
                                            const __nv_bfloat16* Ahp, const __nv_bfloat16* Alp,
                                            const __nv_bfloat16* Bhp, const __nv_bfloat16* Blp,
                                            int kt, int tid) {
    // each tile: 512 16B-chunks / 128 thr = 4 per thread per tile
#pragma unroll
    for (int i = 0; i < 4; i++) {
        const int idx = tid + i * GT;
        const int r = idx >> 2, c = idx & 3;
        const size_t goff = (size_t)r * 1024 + (size_t)kt * 32 + c * 8;
        const uint32_t soff = (uint32_t)(r * 64 + ((c ^ ((r >> 1) & 3)) * 16));
        CP_ASYNC16(sbase + OFF_AH + soff, (const char*)(Ahp + goff));
        CP_ASYNC16(sbase + OFF_AL + soff, (const char*)(Alp + goff));
        CP_ASYNC16(sbase + OFF_BH + soff, (const char*)(Bhp + goff));
        CP_ASYNC16(sbase + OFF_BL + soff, (const char*)(Blp + goff));
    }
}

__global__ __launch_bounds__(GT)
void gemm_qkv(GemmTriple P) {
    extern __shared__ char smc[];
    uint32_t sb = smem_u32(smc);
    const int tid = threadIdx.x;
    const int wid = tid >> 5, lane = tid & 31;
    const int z = blockIdx.z;
    const int m0 = blockIdx.y * BM;
    const int n0 = blockIdx.x * BN;
    const int wm = (wid & 1) * 64;      // 2 m-slots
    const int wn = (wid >> 1) * 64;     // 2 n-slots

    const __nv_bfloat16* Ahp = P.Ah[z] + (size_t)m0 * 1024;
    const __nv_bfloat16* Alp = P.Al[z] + (size_t)m0 * 1024;
    const __nv_bfloat16* Bhp = P.Bh[z] + (size_t)n0 * 1024;
    const __nv_bfloat16* Blp = P.Bl[z] + (size_t)n0 * 1024;

    const int lrow = (lane & 7) + ((lane >> 3) & 1) * 8;
    const int hi5 = (lane >> 4) & 1;   // k-half chunk bit

    float acc[4][8][4];
#pragma unroll
    for (int mt = 0; mt < 4; mt++)
#pragma unroll
        for (int nt = 0; nt < 8; nt++)
#pragma unroll
            for (int q = 0; q < 4; q++) acc[mt][nt][q] = 0.f;

    issue_stage(sb + 0 * STAGE_B, Ahp, Alp, Bhp, Blp, 0, tid);
    CP_COMMIT();
    issue_stage(sb + 1 * STAGE_B, Ahp, Alp, Bhp, Blp, 1, tid);
    CP_COMMIT();

    for (int kt = 0; kt < NK; kt++) {
        CP_WAIT1();            // stage kt landed
        __syncthreads();       // buffer (kt+2)%3 fully consumed (computed in kt-1)
        if (kt + 2 < NK)
            issue_stage(sb + ((kt + 2) % 3) * STAGE_B, Ahp, Alp, Bhp, Blp, kt + 2, tid);
        CP_COMMIT();

        const uint32_t stb = sb + (kt % 3) * STAGE_B;
#pragma unroll
        for (int ks = 0; ks < 2; ks++) {
            uint32_t ah[4][4], al[4][4];
#pragma unroll
            for (int mt = 0; mt < 4; mt++) {
                const int row = wm + mt * 16 + lrow;
                const uint32_t ro = (uint32_t)(row * 64 +
                    (((ks * 2 + hi5) ^ ((row >> 1) & 3)) * 16));
                LDSM_X4(ah[mt][0], ah[mt][1], ah[mt][2], ah[mt][3], stb + OFF_AH + ro);
                LDSM_X4(al[mt][0], al[mt][1], al[mt][2], al[mt][3], stb + OFF_AL + ro);
            }
#pragma unroll
            for (int g = 0; g < 4; g++) {   // four 16-col B groups -> nt = 2g, 2g+1
                const int row = wn + g * 16 + lrow;
                const uint32_t ro = (uint32_t)(row * 64 +
                    (((ks * 2 + hi5) ^ ((row >> 1) & 3)) * 16));
                uint32_t h0, h1, h2, h3, l0, l1, l2, l3;
                LDSM_X4(h0, h1, h2, h3, stb + OFF_BH + ro);
                LDSM_X4(l0, l1, l2, l3, stb + OFF_BL + ro);
                // pass 1: Ah*Bh (8 independent MMAs)
#pragma unroll
                for (int mt = 0; mt < 4; mt++) {
                    MMA_BF16(acc[mt][2 * g + 0], ah[mt], h0, h2);
                    MMA_BF16(acc[mt][2 * g + 1], ah[mt], h1, h3);
                }
                // pass 2: Ah*Bl
#pragma unroll
                for (int mt = 0; mt < 4; mt++) {
                    MMA_BF16(acc[mt][2 * g + 0], ah[mt], l0, l2);
                    MMA_BF16(acc[mt][2 * g + 1], ah[mt], l1, l3);
                }
                // pass 3: Al*Bh
#pragma unroll
                for (int mt = 0; mt < 4; mt++) {
                    MMA_BF16(acc[mt][2 * g + 0], al[mt], h0, h2);
                    MMA_BF16(acc[mt][2 * g + 1], al[mt], h1, h3);
                }
            }
        }
    }

    __nv_bfloat16* Ch = P.Ch[z];
    __nv_bfloat16* Cl = P.Cl[z];
#pragma unroll
    for (int mt = 0; mt < 4; mt++) {
#pragma unroll
        for (int nt = 0; nt < 8; nt++) {
            int row = m0 + wm + mt * 16 + (lane >> 2);
            int col = n0 + wn + nt * 8 + (lane & 3) * 2;
            uint32_t h01, l01, h23, l23;
            pack_split(acc[mt][nt][0], acc[mt][nt][1], h01, l01);
            pack_split(acc[mt][nt][2], acc[mt][nt][3], h23, l23);
            *(uint32_t*)(Ch + (size_t)row * 1024 + col) = h01;
            *(uint32_t*)(Cl + (size_t)row * 1024 + col) = l01;
            *(uint32_t*)(Ch + (size_t)(row + 8) * 1024 + col) = h23;
            *(uint32_t*)(Cl + (size_t)(row + 8) * 1024 + col) = l23;
        }
    }
}

// ================= tensor-core flash attention (bf16 split, fp32 softmax) =================
#define APITCH 72
#define ATILE_B2 (64 * APITCH * 2)    // 9216
#define AQ_H 0
#define AQ_L ATILE_B2
#define AST(s, t) (2 * ATILE_B2 + (s) * (4 * ATILE_B2) + (t) * ATILE_B2)
#define ATTN_SMEM (2 * ATILE_B2 + 2 * 4 * ATILE_B2)   // 92160

__device__ __forceinline__ void attn_load_tile(uint32_t dst, const __nv_bfloat16* src, int tid) {
#pragma unroll
    for (int i = 0; i < 4; i++) {
        int idx = tid + i * 128;
        int r = idx >> 3, c = idx & 7;
        CP_ASYNC16(dst + (uint32_t)(r * 144 + c * 16),
                   (const char*)(src + (size_t)r * 1024 + c * 8));
    }
}

__global__ __launch_bounds__(128, 2)
void attn_mma(const __nv_bfloat16* __restrict__ Qh, const __nv_bfloat16* __restrict__ Ql,
              const __nv_bfloat16* __restrict__ Kh, const __nv_bfloat16* __restrict__ Kl,
              const __nv_bfloat16* __restrict__ Vh, const __nv_bfloat16* __restrict__ Vl,
              float* __restrict__ Of,
              __nv_bfloat16* __restrict__ Oh, __nv_bfloat16* __restrict__ Ol,
              int causal) {
    extern __shared__ char smc[];
    uint32_t sb = smem_u32(smc);
    const int tid = threadIdx.x;
    const int wid = tid >> 5, lane = tid & 31;
    const int q0 = blockIdx.x * 64;
    const int h = blockIdx.y, b = blockIdx.z;
    const size_t rowbase = (size_t)(b * SEQ);
    const int colbase = h * HDIM;

    const int lrow = (lane & 7) + ((lane >> 3) & 1) * 8;
    const int lkof = ((lane >> 4) & 1) * 8;
    const int vrow_l = (lane & 7) + ((lane >> 4) & 1) * 8;
    const int vcol_l = ((lane >> 3) & 1) * 8;

    attn_load_tile(sb + AQ_H, Qh + (rowbase + q0) * 1024 + colbase, tid);
    attn_load_tile(sb + AQ_L, Ql + (rowbase + q0) * 1024 + colbase, tid);
    attn_load_tile(sb + AST(0, 0), Kh + rowbase * 1024 + colbase, tid);
    attn_load_tile(sb + AST(0, 1), Kl + rowbase * 1024 + colbase, tid);
    attn_load_tile(sb + AST(0, 2), Vh + rowbase * 1024 + colbase, tid);
    attn_load_tile(sb + AST(0, 3), Vl + rowbase * 1024 + colbase, tid);
    CP_COMMIT();

    const int njt = causal ? (blockIdx.x + 1) : (SEQ / 64);

    uint32_t qhf[4][4], qlf[4][4];
    float o[8][4];
#pragma unroll
    for (int nt = 0; nt < 8; nt++)
#pragma unroll
        for (int q = 0; q < 4; q++) o[nt][q] = 0.f;
    float m_[2] = {-1e30f, -1e30f}, l_[2] = {0.f, 0.f};

    for (int j = 0; j < njt; j++) {
        CP_WAIT0();
        __syncthreads();
        if (j + 1 < njt) {
            const size_t kb = (rowbase + (size_t)(j + 1) * 64) * 1024 + colbase;
            const int s = (j + 1) & 1;
            attn_load_tile(sb + AST(s, 0), Kh + kb, tid);
            attn_load_tile(sb + AST(s, 1), Kl + kb, tid);
            attn_load_tile(sb + AST(s, 2), Vh + kb, tid);
            attn_load_tile(sb + AST(s, 3), Vl + kb, tid);
            CP_COMMIT();
        }
        if (j == 0) {
#pragma unroll
            for (int kt = 0; kt < 4; kt++) {
                uint32_t ro = (uint32_t)((wid * 16 + lrow) * 144 + (kt * 16 + lkof) * 2);
                LDSM_X4(qhf[kt][0], qhf[kt][1], qhf[kt][2], qhf[kt][3], sb + AQ_H + ro);
                LDSM_X4(qlf[kt][0], qlf[kt][1], qlf[kt][2], qlf[kt][3], sb + AQ_L + ro);
            }
        }

        const uint32_t khb = sb + AST(j & 1, 0);
        const uint32_t klb = sb + AST(j & 1, 1);
        const uint32_t vhb = sb + AST(j & 1, 2);
        const uint32_t vlb = sb + AST(j & 1, 3);

        float s[8][4];
#pragma unroll
        for (int nt = 0; nt < 8; nt++)
#pragma unroll
            for (int q = 0; q < 4; q++) s[nt][q] = 0.f;
#pragma unroll
        for (int kt = 0; kt < 4; kt++) {
            uint32_t bh[8][2], bl[8][2];
#pragma unroll
            for (int g = 0; g < 4; g++) {
                uint32_t ro = (uint32_t)((g * 16 + lrow) * 144 + (kt * 16 + lkof) * 2);
                uint32_t r0, r1, r2, r3;
                LDSM_X4(r0, r1, r2, r3, khb + ro);
                bh[2 * g + 0][0] = r0; bh[2 * g + 0][1] = r2;
                bh[2 * g + 1][0] = r1; bh[2 * g + 1][1] = r3;
                LDSM_X4(r0, r1, r2, r3, klb + ro);
                bl[2 * g + 0][0] = r0; bl[2 * g + 0][1] = r2;
                bl[2 * g + 1][0] = r1; bl[2 * g + 1][1] = r3;
            }
#pragma unroll
            for (int nt = 0; nt < 8; nt++)
                MMA_BF16(s[nt], qhf[kt], bh[nt][0], bh[nt][1]);
#pragma unroll
            for (int nt = 0; nt < 8; nt++)
                MMA_BF16(s[nt], qhf[kt], bl[nt][0], bl[nt][1]);
#pragma unroll
            for (int nt = 0; nt < 8; nt++)
                MMA_BF16(s[nt], qlf[kt], bh[nt][0], bh[nt][1]);
        }

#pragma unroll
        for (int nt = 0; nt < 8; nt++)
#pragma unroll
            for (int q = 0; q < 4; q++) s[nt][q] *= 0.125f;
        if (causal && j == njt - 1) {
            const int r0l = wid * 16 + (lane >> 2), r1l = r0l + 8;
#pragma unroll
            for (int nt = 0; nt < 8; nt++) {
                const int c0 = nt * 8 + (lane & 3) * 2;
                if (c0 > r0l)     s[nt][0] = -1e9f;
                if (c0 + 1 > r0l) s[nt][1] = -1e9f;
                if (c0 > r1l)     s[nt][2] = -1e9f;
                if (c0 + 1 > r1l) s[nt][3] = -1e9f;
            }
        }

        float mx0 = -1e30f, mx1 = -1e30f;
#pragma unroll
        for (int nt = 0; nt < 8; nt++) {
            mx0 = fmaxf(mx0, fmaxf(s[nt][0], s[nt][1]));
            mx1 = fmaxf(mx1, fmaxf(s[nt][2], s[nt][3]));
        }
        mx0 = fmaxf(mx0, __shfl_xor_sync(0xffffffffu, mx0, 1));
        mx0 = fmaxf(mx0, __shfl_xor_sync(0xffffffffu, mx0, 2));
        mx1 = fmaxf(mx1, __shfl_xor_sync(0xffffffffu, mx1, 1));
        mx1 = fmaxf(mx1, __shfl_xor_sync(0xffffffffu, mx1, 2));
        const float mn0 = fmaxf(m_[0], mx0), mn1 = fmaxf(m_[1], mx1);
        const float f0 = __expf(m_[0] - mn0), f1 = __expf(m_[1] - mn1);
        m_[0] = mn0; m_[1] = mn1;
        float rs0 = 0.f, rs1 = 0.f;
#pragma unroll
        for (int nt = 0; nt < 8; nt++) {
            s[nt][0] = __expf(s[nt][0] - mn0);
            s[nt][1] = __expf(s[nt][1] - mn0);
            s[nt][2] = __expf(s[nt][2] - mn1);
            s[nt][3] = __expf(s[nt][3] - mn1);
            rs0 += s[nt][0] + s[nt][1];
            rs1 += s[nt][2] + s[nt][3];
        }
        rs0 += __shfl_xor_sync(0xffffffffu, rs0, 1);
        rs0 += __shfl_xor_sync(0xffffffffu, rs0, 2);
        rs1 += __shfl_xor_sync(0xffffffffu, rs1, 1);
        rs1 += __shfl_xor_sync(0xffffffffu, rs1, 2);
        l_[0] = l_[0] * f0 + rs0;
        l_[1] = l_[1] * f1 + rs1;
#pragma unroll
        for (int nt = 0; nt < 8; nt++) {
            o[nt][0] *= f0; o[nt][1] *= f0; o[nt][2] *= f1; o[nt][3] *= f1;
        }

        uint32_t ph[4][4], pl[4][4];
#pragma unroll
        for (int kt = 0; kt < 4; kt++) {
            pack_split(s[2 * kt][0],     s[2 * kt][1],     ph[kt][0], pl[kt][0]);
            pack_split(s[2 * kt][2],     s[2 * kt][3],     ph[kt][1], pl[kt][1]);
            pack_split(s[2 * kt + 1][0], s[2 * kt + 1][1], ph[kt][2], pl[kt][2]);
            pack_split(s[2 * kt + 1][2], s[2 * kt + 1][3], ph[kt][3], pl[kt][3]);
        }

#pragma unroll
        for (int kt = 0; kt < 4; kt++) {
            const uint32_t vro = (uint32_t)((kt * 16 + vrow_l) * 144);
            uint32_t bh[8][2], bl[8][2];
#pragma unroll
            for (int g = 0; g < 4; g++) {
                uint32_t ro = vro + (uint32_t)((g * 16 + vcol_l) * 2);
                uint32_t r0, r1, r2, r3;
                LDSM_X4_T(r0, r1, r2, r3, vhb + ro);
                bh[2 * g + 0][0] = r0; bh[2 * g + 0][1] = r2;
                bh[2 * g + 1][0] = r1; bh[2 * g + 1][1] = r3;
                LDSM_X4_T(r0, r1, r2, r3, vlb + ro);
                bl[2 * g + 0][0] = r0; bl[2 * g + 0][1] = r2;
                bl[2 * g + 1][0] = r1; bl[2 * g + 1][1] = r3;
            }
#pragma unroll
            for (int nt = 0; nt < 8; nt++)
                MMA_BF16(o[nt], ph[kt], bh[nt][0], bh[nt][1]);
#pragma unroll
            for (int nt = 0; nt < 8; nt++)
                MMA_BF16(o[nt], ph[kt], bl[nt][0], bl[nt][1]);
#pragma unroll
            for (int nt = 0; nt < 8; nt++)
                MMA_BF16(o[nt], pl[kt], bh[nt][0], bh[nt][1]);
        }
    }

    const float inv0 = 1.f / l_[0], inv1 = 1.f / l_[1];
    const size_t row0 = rowbase + q0 + wid * 16 + (lane >> 2);
    const int col = colbase + (lane & 3) * 2;
    if (Of) {
#pragma unroll
        for (int nt = 0; nt < 8; nt++) {
            *(float2*)(Of + row0 * 1024 + col + nt * 8) =
                make_float2(o[nt][0] * inv0, o[nt][1] * inv0);
            *(float2*)(Of + (row0 + 8) * 1024 + col + nt * 8) =
                make_float2(o[nt][2] * inv1, o[nt][3] * inv1);
        }
    } else {
#pragma unroll
        for (int nt = 0; nt < 8; nt++) {
            uint32_t h01, l01, h23, l23;
            pack_split(o[nt][0] * inv0, o[nt][1] * inv0, h01, l01);
            pack_split(o[nt][2] * inv1, o[nt][3] * inv1, h23, l23);
            *(uint32_t*)(Oh + row0 * 1024 + col + nt * 8) = h01;
            *(uint32_t*)(Ol + row0 * 1024 + col + nt * 8) = l01;
            *(uint32_t*)(Oh + (row0 + 8) * 1024 + col + nt * 8) = h23;
            *(uint32_t*)(Ol + (row0 + 8) * 1024 + col + nt * 8) = l23;
        }
    }
}

// ================= launch =================
extern "C" void kernel_launch(void* const* d_in, const int* in_sizes, int n_in,
                              void* d_out, int out_size) {
    const float* x   = (const float*)d_in[0];
    const float* enc = (const float*)d_in[1];
    const float* w[6] = {(const float*)d_in[4], (const float*)d_in[5],
                         (const float*)d_in[6], (const float*)d_in[7],
                         (const float*)d_in[8], (const float*)d_in[9]};
    float* out = (float*)d_out;

    __nv_bfloat16 *qh, *ql, *kh, *kl, *vh, *vl, *ah, *al, *eh, *el, *wh, *wl;
    cudaGetSymbolAddress((void**)&qh, g_qh);
    cudaGetSymbolAddress((void**)&ql, g_ql);
    cudaGetSymbolAddress((void**)&kh, g_kh);
    cudaGetSymbolAddress((void**)&kl, g_kl);
    cudaGetSymbolAddress((void**)&vh, g_vh);
    cudaGetSymbolAddress((void**)&vl, g_vl);
    cudaGetSymbolAddress((void**)&ah, g_ah);
    cudaGetSymbolAddress((void**)&al, g_al);
    cudaGetSymbolAddress((void**)&eh, g_eh);
    cudaGetSymbolAddress((void**)&el, g_el);
    cudaGetSymbolAddress((void**)&wh, g_w6h);
    cudaGetSymbolAddress((void**)&wl, g_w6l);

    cudaFuncSetAttribute(gemm_qkv, cudaFuncAttributeMaxDynamicSharedMemorySize, GEMM_SMEM);
    cudaFuncSetAttribute(attn_mma, cudaFuncAttributeMaxDynamicSharedMemorySize, ATTN_SMEM);

    const size_t WSZ = (size_t)DMODEL * DMODEL;
    const int actBlocks = (MTOT * DMODEL) / (256 * 4);   // 4096
    const int wBlocks   = (int)(WSZ / (256 * 4));        // 1024
    dim3 gg(DMODEL / BN, MTOT / BM, 3);                  // (8, 32, 3)
    dim3 ga(SEQ / 64, NHEAD, BATCH);                     // (16, 16, 4)

    // 5 split launches so gemm_qkv is launch #6 (ncu -s 5 -c 1 profiles it)
    SplitBatch S1 = {}; S1.src[0] = x;   S1.hi[0] = ah; S1.lo[0] = al;
    split_multi<<<dim3(actBlocks, 1), 256>>>(S1);                        // 1
    SplitBatch S2 = {}; S2.src[0] = enc; S2.hi[0] = eh; S2.lo[0] = el;
    split_multi<<<dim3(actBlocks, 1), 256>>>(S2);                        // 2
    for (int p = 0; p < 3; p++) {                                        // 3,4,5
        SplitBatch Sw = {};
        for (int i = 0; i < 2; i++) {
            int wi = p * 2 + i;
            Sw.src[i] = w[wi]; Sw.hi[i] = wh + wi * WSZ; Sw.lo[i] = wl + wi * WSZ;
        }
        split_multi<<<dim3(wBlocks, 2), 256>>>(Sw);
    }

    // ---- self-attention block ----
    GemmTriple Ps;
    for (int zi = 0; zi < 3; zi++) {
        Ps.Ah[zi] = ah; Ps.Al[zi] = al;
        Ps.Bh[zi] = wh + zi * WSZ; Ps.Bl[zi] = wl + zi * WSZ;
    }
    Ps.Ch[0] = qh; Ps.Cl[0] = ql;
    Ps.Ch[1] = kh; Ps.Cl[1] = kl;
    Ps.Ch[2] = vh; Ps.Cl[2] = vl;
    gemm_qkv<<<gg, GT, GEMM_SMEM>>>(Ps);                                 // 6 (profiled)
    attn_mma<<<ga, 128, ATTN_SMEM>>>(qh, ql, kh, kl, vh, vl, nullptr, ah, al, 1);

    // ---- cross-attention block ----
    GemmTriple Pc;
    Pc.Ah[0] = ah; Pc.Al[0] = al;
    Pc.Ah[1] = eh; Pc.Al[1] = el;
    Pc.Ah[2] = eh; Pc.Al[2] = el;
    for (int zi = 0; zi < 3; zi++) {
        Pc.Bh[zi] = wh + (3 + zi) * WSZ; Pc.Bl[zi] = wl + (3 + zi) * WSZ;
    }
    Pc.Ch[0] = qh; Pc.Cl[0] = ql;
    Pc.Ch[1] = kh; Pc.Cl[1] = kl;
    Pc.Ch[2] = vh; Pc.Cl[2] = vl;
    gemm_qkv<<<gg, GT, GEMM_SMEM>>>(Pc);
    attn_mma<<<ga, 128, ATTN_SMEM>>>(qh, ql, kh, kl, vh, vl, out, nullptr, nullptr, 0);
}

// round 15
// speedup vs baseline: 1.1276x; 1.0858x over previous
#include <cuda_runtime.h>
#include <cuda_bf16.h>
#include <cstdint>

// DecoderBlock: self-MHA (causal) -> cross-MHA (no mask).
// B=4, S=1024, D=1024, H=16, DK=64.
// All matmuls mma.sync bf16 hi/lo split (fp32 accum).
// R15: R10 kernels verbatim (best: 784us). NEW: cross-K/V GEMM gets its own
//      buffers + second stream, overlapping with self-attention (fork/join events).

#define SEQ    1024
#define DMODEL 1024
#define NHEAD  16
#define HDIM   64
#define BATCH  4
#define MTOT   (BATCH * SEQ)   // 4096

// ---------------- scratch ----------------
__device__ __nv_bfloat16 g_qh[(size_t)MTOT * DMODEL];
__device__ __nv_bfloat16 g_ql[(size_t)MTOT * DMODEL];
__device__ __nv_bfloat16 g_kh[(size_t)MTOT * DMODEL];
__device__ __nv_bfloat16 g_kl[(size_t)MTOT * DMODEL];
__device__ __nv_bfloat16 g_vh[(size_t)MTOT * DMODEL];
__device__ __nv_bfloat16 g_vl[(size_t)MTOT * DMODEL];
__device__ __nv_bfloat16 g_kh2[(size_t)MTOT * DMODEL];   // cross K/V (no WAR with attn_self)
__device__ __nv_bfloat16 g_kl2[(size_t)MTOT * DMODEL];
__device__ __nv_bfloat16 g_vh2[(size_t)MTOT * DMODEL];
__device__ __nv_bfloat16 g_vl2[(size_t)MTOT * DMODEL];
__device__ __nv_bfloat16 g_ah[(size_t)MTOT * DMODEL];
__device__ __nv_bfloat16 g_al[(size_t)MTOT * DMODEL];
__device__ __nv_bfloat16 g_eh[(size_t)MTOT * DMODEL];
__device__ __nv_bfloat16 g_el[(size_t)MTOT * DMODEL];
__device__ __nv_bfloat16 g_w6h[6 * (size_t)DMODEL * DMODEL];
__device__ __nv_bfloat16 g_w6l[6 * (size_t)DMODEL * DMODEL];

// ================= PTX helpers =================
__device__ __forceinline__ uint32_t smem_u32(const void* p) {
    uint32_t a;
    asm("{ .reg .u64 t; cvta.to.shared.u64 t, %1; cvt.u32.u64 %0, t; }" : "=r"(a) : "l"(p));
    return a;
}
#define CP_ASYNC16(dst, src) asm volatile("cp.async.cg.shared.global [%0], [%1], 16;" :: "r"(dst), "l"(src))
#define CP_COMMIT()  asm volatile("cp.async.commit_group;" ::: "memory")
#define CP_WAIT1()   asm volatile("cp.async.wait_group 1;" ::: "memory")
#define CP_WAIT0()   asm volatile("cp.async.wait_group 0;" ::: "memory")

#define LDSM_X4(r0, r1, r2, r3, addr) \
    asm volatile("ldmatrix.sync.aligned.m8n8.x4.shared.b16 {%0,%1,%2,%3}, [%4];" \
                 : "=r"(r0), "=r"(r1), "=r"(r2), "=r"(r3) : "r"(addr))
#define LDSM_X4_T(r0, r1, r2, r3, addr) \
    asm volatile("ldmatrix.sync.aligned.m8n8.x4.trans.shared.b16 {%0,%1,%2,%3}, [%4];" \
                 : "=r"(r0), "=r"(r1), "=r"(r2), "=r"(r3) : "r"(addr))

#define MMA_BF16(c, a, b0v, b1v) \
    asm volatile("mma.sync.aligned.m16n8k16.row.col.f32.bf16.bf16.f32 " \
                 "{%0,%1,%2,%3}, {%4,%5,%6,%7}, {%8,%9}, {%0,%1,%2,%3};" \
                 : "+f"((c)[0]), "+f"((c)[1]), "+f"((c)[2]), "+f"((c)[3]) \
                 : "r"((a)[0]), "r"((a)[1]), "r"((a)[2]), "r"((a)[3]), \
                   "r"(b0v), "r"(b1v))

__device__ __forceinline__ void pack_split(float a, float b, uint32_t& h, uint32_t& l) {
    __nv_bfloat16 ha = __float2bfloat16(a), hb = __float2bfloat16(b);
    float ra = a - __bfloat162float(ha), rb = b - __bfloat162float(hb);
    __nv_bfloat162 hh = __halves2bfloat162(ha, hb);
    __nv_bfloat162 ll = __halves2bfloat162(__float2bfloat16(ra), __float2bfloat16(rb));
    h = *reinterpret_cast<uint32_t*>(&hh);
    l = *reinterpret_cast<uint32_t*>(&ll);
}

// ================= batched split fp32 -> bf16 hi/lo =================
struct SplitBatch {
    const float* src[6];
    __nv_bfloat16* hi[6];
    __nv_bfloat16* lo[6];
};

__global__ __launch_bounds__(256) void split_multi(SplitBatch S) {
    const float* x = S.src[blockIdx.y];
    __nv_bfloat16* hi = S.hi[blockIdx.y];
    __nv_bfloat16* lo = S.lo[blockIdx.y];
    size_t i = ((size_t)blockIdx.x * 256 + threadIdx.x) * 4;
    float4 v = *(const float4*)(x + i);
    uint32_t h0, l0, h1, l1;
    pack_split(v.x, v.y, h0, l0);
    pack_split(v.z, v.w, h1, l1);
    *(uint32_t*)(hi + i)     = h0; *(uint32_t*)(hi + i + 2) = h1;
    *(uint32_t*)(lo + i)     = l0; *(uint32_t*)(lo + i + 2) = l1;
}

// ================= fused-split mma.sync GEMM (R10 config, best known) =================
// C = A * B^T (4096x1024x1024) per z; 3 passes ordered pass-outer.
// CTA 128x128, 8 warps @64x32. 3-stage cp.async, XOR-swizzled 64B rows,
// 96KB smem -> 2 CTAs/SM, one barrier per k-tile.
#define BM 128
#define BN 128
#define GT 256
#define TILE_B 8192                    // 128 rows * 64B
#define STAGE_B (4 * TILE_B)           // Ah, Al, Bh, Bl = 32768
#define NK 32
#define GEMM_SMEM (3 * STAGE_B)        // 98304

struct GemmTriple {
    const __nv_bfloat16* Ah[3];
    const __nv_bfloat16* Al[3];
    const __nv_bfloat16* Bh[3];
    const __nv_bfloat16* Bl[3];
    __nv_bfloat16* Ch[3];
    __nv_bfloat16* Cl[3];
};

__device__ __forceinline__ void issue_stage(uint32_t sbase,
                                            const __nv_bfloat16* Ahp, const __nv_bfloat16* Alp,
                                            const __nv_bfloat16* Bhp, const __nv_bfloat16* Blp,
                                            int kt, int tid) {
#pragma unroll
    for (int i = 0; i < 2; i++) {
        const int idx = tid + i * GT;                  // 0..511
        const int r = idx >> 2, c = idx & 3;
        const size_t goff = (size_t)r * 1024 + (size_t)kt * 32 + c * 8;
        const uint32_t soff = (uint32_t)(r * 64 + ((c ^ ((r >> 1) & 3)) * 16));
        CP_ASYNC16(sbase + 0 * TILE_B + soff, (const char*)(Ahp + goff));
        CP_ASYNC16(sbase + 1 * TILE_B + soff, (const char*)(Alp + goff));
        CP_ASYNC16(sbase + 2 * TILE_B + soff, (const char*)(Bhp + goff));
        CP_ASYNC16(sbase + 3 * TILE_B + soff, (const char*)(Blp + goff));
    }
}

__global__ __launch_bounds__(GT, 2)
void gemm_qkv(GemmTriple P) {
    extern __shared__ char smc[];
    uint32_t sb = smem_u32(smc);
    const int tid = threadIdx.x;
    const int wid = tid >> 5, lane = tid & 31;
    const int z = blockIdx.z;
    const int m0 = blockIdx.y * BM;
    const int n0 = blockIdx.x * BN;
    const int wm = (wid & 1) * 64;
    const int wn = (wid >> 1) * 32;

    const __nv_bfloat16* Ahp = P.Ah[z] + (size_t)m0 * 1024;
    const __nv_bfloat16* Alp = P.Al[z] + (size_t)m0 * 1024;
    const __nv_bfloat16* Bhp = P.Bh[z] + (size_t)n0 * 1024;
    const __nv_bfloat16* Blp = P.Bl[z] + (size_t)n0 * 1024;

    const int lrow = (lane & 7) + ((lane >> 3) & 1) * 8;
    const int hi5 = (lane >> 4) & 1;   // k-half chunk bit

    float acc[4][4][4];
#pragma unroll
    for (int mt = 0; mt < 4; mt++)
#pragma unroll
        for (int nt = 0; nt < 4; nt++)
#pragma unroll
            for (int q = 0; q < 4; q++) acc[mt][nt][q] = 0.f;

    issue_stage(sb + 0 * STAGE_B, Ahp, Alp, Bhp, Blp, 0, tid);
    CP_COMMIT();
    issue_stage(sb + 1 * STAGE_B, Ahp, Alp, Bhp, Blp, 1, tid);
    CP_COMMIT();

    for (int kt = 0; kt < NK; kt++) {
        CP_WAIT1();            // stage kt landed
        __syncthreads();       // buffer (kt+2)%3 fully consumed (computed in kt-1)
        if (kt + 2 < NK)
            issue_stage(sb + ((kt + 2) % 3) * STAGE_B, Ahp, Alp, Bhp, Blp, kt + 2, tid);
        CP_COMMIT();

        const uint32_t stb = sb + (kt % 3) * STAGE_B;
#pragma unroll
        for (int ks = 0; ks < 2; ks++) {
            uint32_t ah[4][4], al[4][4];
#pragma unroll
            for (int mt = 0; mt < 4; mt++) {
                const int row = wm + mt * 16 + lrow;
                const uint32_t ro = (uint32_t)(row * 64 +
                    (((ks * 2 + hi5) ^ ((row >> 1) & 3)) * 16));
                LDSM_X4(ah[mt][0], ah[mt][1], ah[mt][2], ah[mt][3], stb + ro);
                LDSM_X4(al[mt][0], al[mt][1], al[mt][2], al[mt][3], stb + TILE_B + ro);
            }
#pragma unroll
            for (int g = 0; g < 2; g++) {   // two 16-col B groups -> nt = 2g, 2g+1
                const int row = wn + g * 16 + lrow;
                const uint32_t ro = (uint32_t)(row * 64 +
                    (((ks * 2 + hi5) ^ ((row >> 1) & 3)) * 16));
                uint32_t h0, h1, h2, h3, l0, l1, l2, l3;
                LDSM_X4(h0, h1, h2, h3, stb + 2 * TILE_B + ro);
                LDSM_X4(l0, l1, l2, l3, stb + 3 * TILE_B + ro);
                // pass 1: Ah * Bh  (8 independent MMAs)
#pragma unroll
                for (int mt = 0; mt < 4; mt++) {
                    MMA_BF16(acc[mt][2 * g + 0], ah[mt], h0, h2);
                    MMA_BF16(acc[mt][2 * g + 1], ah[mt], h1, h3);
                }
                // pass 2: Ah * Bl
#pragma unroll
                for (int mt = 0; mt < 4; mt++) {
                    MMA_BF16(acc[mt][2 * g + 0], ah[mt], l0, l2);
                    MMA_BF16(acc[mt][2 * g + 1], ah[mt], l1, l3);
                }
                // pass 3: Al * Bh
#pragma unroll
                for (int mt = 0; mt < 4; mt++) {
                    MMA_BF16(acc[mt][2 * g + 0], al[mt], h0, h2);
                    MMA_BF16(acc[mt][2 * g + 1], al[mt], h1, h3);
                }
            }
        }
    }

    __nv_bfloat16* Ch = P.Ch[z];
    __nv_bfloat16* Cl = P.Cl[z];
#pragma unroll
    for (int mt = 0; mt < 4; mt++) {
#pragma unroll
        for (int nt = 0; nt < 4; nt++) {
            int row = m0 + wm + mt * 16 + (lane >> 2);
            int col = n0 + wn + nt * 8 + (lane & 3) * 2;
            uint32_t h01, l01, h23, l23;
            pack_split(acc[mt][nt][0], acc[mt][nt][1], h01, l01);
            pack_split(acc[mt][nt][2], acc[mt][nt][3], h23, l23);
            *(uint32_t*)(Ch + (size_t)row * 1024 + col) = h01;
            *(uint32_t*)(Cl + (size_t)row * 1024 + col) = l01;
            *(uint32_t*)(Ch + (size_t)(row + 8) * 1024 + col) = h23;
            *(uint32_t*)(Cl + (size_t)(row + 8) * 1024 + col) = l23;
        }
    }
}

// ================= tensor-core flash attention (bf16 split, fp32 softmax) =================
#define APITCH 72
#define ATILE_B2 (64 * APITCH * 2)    // 9216
#define AQ_H 0
#define AQ_L ATILE_B2
#define AST(s, t) (2 * ATILE_B2 + (s) * (4 * ATILE_B2) + (t) * ATILE_B2)
#define ATTN_SMEM (2 * ATILE_B2 + 2 * 4 * ATILE_B2)   // 92160

__device__ __forceinline__ void attn_load_tile(uint32_t dst, const __nv_bfloat16* src, int tid) {
#pragma unroll
    for (int i = 0; i < 4; i++) {
        int idx = tid + i * 128;
        int r = idx >> 3, c = idx & 7;
        CP_ASYNC16(dst + (uint32_t)(r * 144 + c * 16),
                   (const char*)(src + (size_t)r * 1024 + c * 8));
    }
}

__global__ __launch_bounds__(128, 2)
void attn_mma(const __nv_bfloat16* __restrict__ Qh, const __nv_bfloat16* __restrict__ Ql,
              const __nv_bfloat16* __restrict__ Kh, const __nv_bfloat16* __restrict__ Kl,
              const __nv_bfloat16* __restrict__ Vh, const __nv_bfloat16* __restrict__ Vl,
              float* __restrict__ Of,
              __nv_bfloat16* __restrict__ Oh, __nv_bfloat16* __restrict__ Ol,
              int causal) {
    extern __shared__ char smc[];
    uint32_t sb = smem_u32(smc);
    const int tid = threadIdx.x;
    const int wid = tid >> 5, lane = tid & 31;
    const int q0 = blockIdx.x * 64;
    const int h = blockIdx.y, b = blockIdx.z;
    const size_t rowbase = (size_t)(b * SEQ);
    const int colbase = h * HDIM;

    const int lrow = (lane & 7) + ((lane >> 3) & 1) * 8;
    const int lkof = ((lane >> 4) & 1) * 8;
    const int vrow_l = (lane & 7) + ((lane >> 4) & 1) * 8;
    const int vcol_l = ((lane >> 3) & 1) * 8;

    attn_load_tile(sb + AQ_H, Qh + (rowbase + q0) * 1024 + colbase, tid);
    attn_load_tile(sb + AQ_L, Ql + (rowbase + q0) * 1024 + colbase, tid);
    attn_load_tile(sb + AST(0, 0), Kh + rowbase * 1024 + colbase, tid);
    attn_load_tile(sb + AST(0, 1), Kl + rowbase * 1024 + colbase, tid);
    attn_load_tile(sb + AST(0, 2), Vh + rowbase * 1024 + colbase, tid);
    attn_load_tile(sb + AST(0, 3), Vl + rowbase * 1024 + colbase, tid);
    CP_COMMIT();

    const int njt = causal ? (blockIdx.x + 1) : (SEQ / 64);

    uint32_t qhf[4][4], qlf[4][4];
    float o[8][4];
#pragma unroll
    for (int nt = 0; nt < 8; nt++)
#pragma unroll
        for (int q = 0; q < 4; q++) o[nt][q] = 0.f;
    float m_[2] = {-1e30f, -1e30f}, l_[2] = {0.f, 0.f};

    for (int j = 0; j < njt; j++) {
        CP_WAIT0();
        __syncthreads();
        if (j + 1 < njt) {
            const size_t kb = (rowbase + (size_t)(j + 1) * 64) * 1024 + colbase;
            const int s = (j + 1) & 1;
            attn_load_tile(sb + AST(s, 0), Kh + kb, tid);
            attn_load_tile(sb + AST(s, 1), Kl + kb, tid);
            attn_load_tile(sb + AST(s, 2), Vh + kb, tid);
            attn_load_tile(sb + AST(s, 3), Vl + kb, tid);
            CP_COMMIT();
        }
        if (j == 0) {
#pragma unroll
            for (int kt = 0; kt < 4; kt++) {
                uint32_t ro = (uint32_t)((wid * 16 + lrow) * 144 + (kt * 16 + lkof) * 2);
                LDSM_X4(qhf[kt][0], qhf[kt][1], qhf[kt][2], qhf[kt][3], sb + AQ_H + ro);
                LDSM_X4(qlf[kt][0], qlf[kt][1], qlf[kt][2], qlf[kt][3], sb + AQ_L + ro);
            }
        }

        const uint32_t khb = sb + AST(j & 1, 0);
        const uint32_t klb = sb + AST(j & 1, 1);
        const uint32_t vhb = sb + AST(j & 1, 2);
        const uint32_t vlb = sb + AST(j & 1, 3);

        float s[8][4];
#pragma unroll
        for (int nt = 0; nt < 8; nt++)
#pragma unroll
            for (int q = 0; q < 4; q++) s[nt][q] = 0.f;
#pragma unroll
        for (int kt = 0; kt < 4; kt++) {
            uint32_t bh[8][2], bl[8][2];
#pragma unroll
            for (int g = 0; g < 4; g++) {
                uint32_t ro = (uint32_t)((g * 16 + lrow) * 144 + (kt * 16 + lkof) * 2);
                uint32_t r0, r1, r2, r3;
                LDSM_X4(r0, r1, r2, r3, khb + ro);
                bh[2 * g + 0][0] = r0; bh[2 * g + 0][1] = r2;
                bh[2 * g + 1][0] = r1; bh[2 * g + 1][1] = r3;
                LDSM_X4(r0, r1, r2, r3, klb + ro);
                bl[2 * g + 0][0] = r0; bl[2 * g + 0][1] = r2;
                bl[2 * g + 1][0] = r1; bl[2 * g + 1][1] = r3;
            }
#pragma unroll
            for (int nt = 0; nt < 8; nt++)
                MMA_BF16(s[nt], qhf[kt], bh[nt][0], bh[nt][1]);
#pragma unroll
            for (int nt = 0; nt < 8; nt++)
                MMA_BF16(s[nt], qhf[kt], bl[nt][0], bl[nt][1]);
#pragma unroll
            for (int nt = 0; nt < 8; nt++)
                MMA_BF16(s[nt], qlf[kt], bh[nt][0], bh[nt][1]);
        }

#pragma unroll
        for (int nt = 0; nt < 8; nt++)
#pragma unroll
            for (int q = 0; q < 4; q++) s[nt][q] *= 0.125f;
        if (causal && j == njt - 1) {
            const int r0l = wid * 16 + (lane >> 2), r1l = r0l + 8;
#pragma unroll
            for (int nt = 0; nt < 8; nt++) {
                const int c0 = nt * 8 + (lane & 3) * 2;
                if (c0 > r0l)     s[nt][0] = -1e9f;
                if (c0 + 1 > r0l) s[nt][1] = -1e9f;
                if (c0 > r1l)     s[nt][2] = -1e9f;
                if (c0 + 1 > r1l) s[nt][3] = -1e9f;
            }
        }

        float mx0 = -1e30f, mx1 = -1e30f;
#pragma unroll
        for (int nt = 0; nt < 8; nt++) {
            mx0 = fmaxf(mx0, fmaxf(s[nt][0], s[nt][1]));
            mx1 = fmaxf(mx1, fmaxf(s[nt][2], s[nt][3]));
        }
        mx0 = fmaxf(mx0, __shfl_xor_sync(0xffffffffu, mx0, 1));
        mx0 = fmaxf(mx0, __shfl_xor_sync(0xffffffffu, mx0, 2));
        mx1 = fmaxf(mx1, __shfl_xor_sync(0xffffffffu, mx1, 1));
        mx1 = fmaxf(mx1, __shfl_xor_sync(0xffffffffu, mx1, 2));
        const float mn0 = fmaxf(m_[0], mx0), mn1 = fmaxf(m_[1], mx1);
        const float f0 = __expf(m_[0] - mn0), f1 = __expf(m_[1] - mn1);
        m_[0] = mn0; m_[1] = mn1;
        float rs0 = 0.f, rs1 = 0.f;
#pragma unroll
        for (int nt = 0; nt < 8; nt++) {
            s[nt][0] = __expf(s[nt][0] - mn0);
            s[nt][1] = __expf(s[nt][1] - mn0);
            s[nt][2] = __expf(s[nt][2] - mn1);
            s[nt][3] = __expf(s[nt][3] - mn1);
            rs0 += s[nt][0] + s[nt][1];
            rs1 += s[nt][2] + s[nt][3];
        }
        rs0 += __shfl_xor_sync(0xffffffffu, rs0, 1);
        rs0 += __shfl_xor_sync(0xffffffffu, rs0, 2);
        rs1 += __shfl_xor_sync(0xffffffffu, rs1, 1);
        rs1 += __shfl_xor_sync(0xffffffffu, rs1, 2);
        l_[0] = l_[0] * f0 + rs0;
        l_[1] = l_[1] * f1 + rs1;
#pragma unroll
        for (int nt = 0; nt < 8; nt++) {
            o[nt][0] *= f0; o[nt][1] *= f0; o[nt][2] *= f1; o[nt][3] *= f1;
        }

        uint32_t ph[4][4], pl[4][4];
#pragma unroll
        for (int kt = 0; kt < 4; kt++) {
            pack_split(s[2 * kt][0],     s[2 * kt][1],     ph[kt][0], pl[kt][0]);
            pack_split(s[2 * kt][2],     s[2 * kt][3],     ph[kt][1], pl[kt][1]);
            pack_split(s[2 * kt + 1][0], s[2 * kt + 1][1], ph[kt][2], pl[kt][2]);
            pack_split(s[2 * kt + 1][2], s[2 * kt + 1][3], ph[kt][3], pl[kt][3]);
        }

#pragma unroll
        for (int kt = 0; kt < 4; kt++) {
            const uint32_t vro = (uint32_t)((kt * 16 + vrow_l) * 144);
            uint32_t bh[8][2], bl[8][2];
#pragma unroll
            for (int g = 0; g < 4; g++) {
                uint32_t ro = vro + (uint32_t)((g * 16 + vcol_l) * 2);
                uint32_t r0, r1, r2, r3;
                LDSM_X4_T(r0, r1, r2, r3, vhb + ro);
                bh[2 * g + 0][0] = r0; bh[2 * g + 0][1] = r2;
                bh[2 * g + 1][0] = r1; bh[2 * g + 1][1] = r3;
                LDSM_X4_T(r0, r1, r2, r3, vlb + ro);
                bl[2 * g + 0][0] = r0; bl[2 * g + 0][1] = r2;
                bl[2 * g + 1][0] = r1; bl[2 * g + 1][1] = r3;
            }
#pragma unroll
            for (int nt = 0; nt < 8; nt++)
                MMA_BF16(o[nt], ph[kt], bh[nt][0], bh[nt][1]);
#pragma unroll
            for (int nt = 0; nt < 8; nt++)
                MMA_BF16(o[nt], ph[kt], bl[nt][0], bl[nt][1]);
#pragma unroll
            for (int nt = 0; nt < 8; nt++)
                MMA_BF16(o[nt], pl[kt], bh[nt][0], bh[nt][1]);
        }
    }

    const float inv0 = 1.f / l_[0], inv1 = 1.f / l_[1];
    const size_t row0 = rowbase + q0 + wid * 16 + (lane >> 2);
    const int col = colbase + (lane & 3) * 2;
    if (Of) {
#pragma unroll
        for (int nt = 0; nt < 8; nt++) {
            *(float2*)(Of + row0 * 1024 + col + nt * 8) =
                make_float2(o[nt][0] * inv0, o[nt][1] * inv0);
            *(float2*)(Of + (row0 + 8) * 1024 + col + nt * 8) =
                make_float2(o[nt][2] * inv1, o[nt][3] * inv1);
        }
    } else {
#pragma unroll
        for (int nt = 0; nt < 8; nt++) {
            uint32_t h01, l01, h23, l23;
            pack_split(o[nt][0] * inv0, o[nt][1] * inv0, h01, l01);
            pack_split(o[nt][2] * inv1, o[nt][3] * inv1, h23, l23);
            *(uint32_t*)(Oh + row0 * 1024 + col + nt * 8) = h01;
            *(uint32_t*)(Ol + row0 * 1024 + col + nt * 8) = l01;
            *(uint32_t*)(Oh + (row0 + 8) * 1024 + col + nt * 8) = h23;
            *(uint32_t*)(Ol + (row0 + 8) * 1024 + col + nt * 8) = l23;
        }
    }
}

// ================= launch =================
extern "C" void kernel_launch(void* const* d_in, const int* in_sizes, int n_in,
                              void* d_out, int out_size) {
    const float* x   = (const float*)d_in[0];
    const float* enc = (const float*)d_in[1];
    const float* w[6] = {(const float*)d_in[4], (const float*)d_in[5],
                         (const float*)d_in[6], (const float*)d_in[7],
                         (const float*)d_in[8], (const float*)d_in[9]};
    float* out = (float*)d_out;

    __nv_bfloat16 *qh, *ql, *kh, *kl, *vh, *vl, *kh2, *kl2, *vh2, *vl2;
    __nv_bfloat16 *ah, *al, *eh, *el, *wh, *wl;
    cudaGetSymbolAddress((void**)&qh, g_qh);
    cudaGetSymbolAddress((void**)&ql, g_ql);
    cudaGetSymbolAddress((void**)&kh, g_kh);
    cudaGetSymbolAddress((void**)&kl, g_kl);
    cudaGetSymbolAddress((void**)&vh, g_vh);
    cudaGetSymbolAddress((void**)&vl, g_vl);
    cudaGetSymbolAddress((void**)&kh2, g_kh2);
    cudaGetSymbolAddress((void**)&kl2, g_kl2);
    cudaGetSymbolAddress((void**)&vh2, g_vh2);
    cudaGetSymbolAddress((void**)&vl2, g_vl2);
    cudaGetSymbolAddress((void**)&ah, g_ah);
    cudaGetSymbolAddress((void**)&al, g_al);
    cudaGetSymbolAddress((void**)&eh, g_eh);
    cudaGetSymbolAddress((void**)&el, g_el);
    cudaGetSymbolAddress((void**)&wh, g_w6h);
    cudaGetSymbolAddress((void**)&wl, g_w6l);

    cudaFuncSetAttribute(gemm_qkv, cudaFuncAttributeMaxDynamicSharedMemorySize, GEMM_SMEM);
    cudaFuncSetAttribute(attn_mma, cudaFuncAttributeMaxDynamicSharedMemorySize, ATTN_SMEM);

    // lazily-created stream/events (exist before graph capture; creation itself
    // happens on the uncaptured correctness call)
    static cudaStream_t s1 = nullptr;
    static cudaEvent_t ev_fork = nullptr, ev_kv = nullptr;
    if (!s1) {
        cudaStreamCreateWithFlags(&s1, cudaStreamNonBlocking);
        cudaEventCreateWithFlags(&ev_fork, cudaEventDisableTiming);
        cudaEventCreateWithFlags(&ev_kv, cudaEventDisableTiming);
    }

    const size_t WSZ = (size_t)DMODEL * DMODEL;
    dim3 gg3(DMODEL / BN, MTOT / BM, 3);                 // (8, 32, 3)
    dim3 gg2(DMODEL / BN, MTOT / BM, 2);                 // cross K,V
    dim3 gg1(DMODEL / BN, MTOT / BM, 1);                 // cross Q
    dim3 ga(SEQ / 64, NHEAD, BATCH);                     // (16, 16, 4)

    // ---- splits (default stream) ----
    SplitBatch Sa = {};
    Sa.src[0] = x;   Sa.hi[0] = ah; Sa.lo[0] = al;
    Sa.src[1] = enc; Sa.hi[1] = eh; Sa.lo[1] = el;
    split_multi<<<dim3((MTOT * DMODEL) / (256 * 4), 2), 256>>>(Sa);

    SplitBatch Sw = {};
    for (int i = 0; i < 6; i++) {
        Sw.src[i] = w[i]; Sw.hi[i] = wh + i * WSZ; Sw.lo[i] = wl + i * WSZ;
    }
    split_multi<<<dim3((int)(WSZ / (256 * 4)), 6), 256>>>(Sw);

    // ---- fork: s1 runs cross-K/V GEMM concurrently with self block ----
    cudaEventRecord(ev_fork, 0);
    cudaStreamWaitEvent(s1, ev_fork, 0);

    GemmTriple Pkv;
    Pkv.Ah[0] = eh; Pkv.Al[0] = el;     // cross K
    Pkv.Ah[1] = eh; Pkv.Al[1] = el;     // cross V
    Pkv.Bh[0] = wh + 4 * WSZ; Pkv.Bl[0] = wl + 4 * WSZ;
    Pkv.Bh[1] = wh + 5 * WSZ; Pkv.Bl[1] = wl + 5 * WSZ;
    Pkv.Ch[0] = kh2; Pkv.Cl[0] = kl2;
    Pkv.Ch[1] = vh2; Pkv.Cl[1] = vl2;
    gemm_qkv<<<gg2, GT, GEMM_SMEM, s1>>>(Pkv);
    cudaEventRecord(ev_kv, s1);

    // ---- self block (default stream) ----
    GemmTriple Ps;
    for (int zi = 0; zi < 3; zi++) {
        Ps.Ah[zi] = ah; Ps.Al[zi] = al;
        Ps.Bh[zi] = wh + zi * WSZ; Ps.Bl[zi] = wl + zi * WSZ;
    }
    Ps.Ch[0] = qh; Ps.Cl[0] = ql;
    Ps.Ch[1] = kh; Ps.Cl[1] = kl;
    Ps.Ch[2] = vh; Ps.Cl[2] = vl;
    gemm_qkv<<<gg3, GT, GEMM_SMEM>>>(Ps);
    attn_mma<<<ga, 128, ATTN_SMEM>>>(qh, ql, kh, kl, vh, vl, nullptr, ah, al, 1);

    // ---- cross Q GEMM (depends on attn_self output in ah/al) ----
    GemmTriple Pq;
    Pq.Ah[0] = ah; Pq.Al[0] = al;
    Pq.Bh[0] = wh + 3 * WSZ; Pq.Bl[0] = wl + 3 * WSZ;
    Pq.Ch[0] = qh; Pq.Cl[0] = ql;
    gemm_qkv<<<gg1, GT, GEMM_SMEM>>>(Pq);

    // ---- join, then cross attention ----
    cudaStreamWaitEvent(0, ev_kv, 0);
    attn_mma<<<ga, 128, ATTN_SMEM>>>(qh, ql, kh2, kl2, vh2, vl2, out, nullptr, nullptr, 0);
}

// round 16
// speedup vs baseline: 1.3945x; 1.2368x over previous
#include <cuda_runtime.h>
#include <cuda_bf16.h>
#include <cuda_fp16.h>
#include <cstdint>

// DecoderBlock: self-MHA (causal) -> cross-MHA (no mask).
// B=4, S=1024, D=1024, H=16, DK=64.
// R16: GEMMs switch to fp16 2-pass: C = fp16(A) * (Bh + Bl), A unsplit
//      (fp16 rounding err ~2.8e-4), B split hi/lo fp16. MMA work x2/3,
//      A smem traffic halved. Attention stays bf16 3-pass (85% roofline).
//      Stream overlap from R15 kept.

#define SEQ    1024
#define DMODEL 1024
#define NHEAD  16
#define HDIM   64
#define BATCH  4
#define MTOT   (BATCH * SEQ)   // 4096

// ---------------- scratch ----------------
__device__ __nv_bfloat16 g_qh[(size_t)MTOT * DMODEL];
__device__ __nv_bfloat16 g_ql[(size_t)MTOT * DMODEL];
__device__ __nv_bfloat16 g_kh[(size_t)MTOT * DMODEL];
__device__ __nv_bfloat16 g_kl[(size_t)MTOT * DMODEL];
__device__ __nv_bfloat16 g_vh[(size_t)MTOT * DMODEL];
__device__ __nv_bfloat16 g_vl[(size_t)MTOT * DMODEL];
__device__ __nv_bfloat16 g_kh2[(size_t)MTOT * DMODEL];
__device__ __nv_bfloat16 g_kl2[(size_t)MTOT * DMODEL];
__device__ __nv_bfloat16 g_vh2[(size_t)MTOT * DMODEL];
__device__ __nv_bfloat16 g_vl2[(size_t)MTOT * DMODEL];
__device__ __half g_xa[(size_t)MTOT * DMODEL];           // fp16(x)
__device__ __half g_ea[(size_t)MTOT * DMODEL];           // fp16(enc)
__device__ __half g_sa[(size_t)MTOT * DMODEL];           // fp16(attn_self out)
__device__ __half g_w6h[6 * (size_t)DMODEL * DMODEL];
__device__ __half g_w6l[6 * (size_t)DMODEL * DMODEL];

// ================= PTX helpers =================
__device__ __forceinline__ uint32_t smem_u32(const void* p) {
    uint32_t a;
    asm("{ .reg .u64 t; cvta.to.shared.u64 t, %1; cvt.u32.u64 %0, t; }" : "=r"(a) : "l"(p));
    return a;
}
#define CP_ASYNC16(dst, src) asm volatile("cp.async.cg.shared.global [%0], [%1], 16;" :: "r"(dst), "l"(src))
#define CP_COMMIT()  asm volatile("cp.async.commit_group;" ::: "memory")
#define CP_WAIT1()   asm volatile("cp.async.wait_group 1;" ::: "memory")
#define CP_WAIT0()   asm volatile("cp.async.wait_group 0;" ::: "memory")

#define LDSM_X4(r0, r1, r2, r3, addr) \
    asm volatile("ldmatrix.sync.aligned.m8n8.x4.shared.b16 {%0,%1,%2,%3}, [%4];" \
                 : "=r"(r0), "=r"(r1), "=r"(r2), "=r"(r3) : "r"(addr))
#define LDSM_X4_T(r0, r1, r2, r3, addr) \
    asm volatile("ldmatrix.sync.aligned.m8n8.x4.trans.shared.b16 {%0,%1,%2,%3}, [%4];" \
                 : "=r"(r0), "=r"(r1), "=r"(r2), "=r"(r3) : "r"(addr))

#define MMA_BF16(c, a, b0v, b1v) \
    asm volatile("mma.sync.aligned.m16n8k16.row.col.f32.bf16.bf16.f32 " \
                 "{%0,%1,%2,%3}, {%4,%5,%6,%7}, {%8,%9}, {%0,%1,%2,%3};" \
                 : "+f"((c)[0]), "+f"((c)[1]), "+f"((c)[2]), "+f"((c)[3]) \
                 : "r"((a)[0]), "r"((a)[1]), "r"((a)[2]), "r"((a)[3]), \
                   "r"(b0v), "r"(b1v))

#define MMA_F16(c, a, b0v, b1v) \
    asm volatile("mma.sync.aligned.m16n8k16.row.col.f32.f16.f16.f32 " \
                 "{%0,%1,%2,%3}, {%4,%5,%6,%7}, {%8,%9}, {%0,%1,%2,%3};" \
                 : "+f"((c)[0]), "+f"((c)[1]), "+f"((c)[2]), "+f"((c)[3]) \
                 : "r"((a)[0]), "r"((a)[1]), "r"((a)[2]), "r"((a)[3]), \
                   "r"(b0v), "r"(b1v))

__device__ __forceinline__ void pack_split(float a, float b, uint32_t& h, uint32_t& l) {
    __nv_bfloat16 ha = __float2bfloat16(a), hb = __float2bfloat16(b);
    float ra = a - __bfloat162float(ha), rb = b - __bfloat162float(hb);
    __nv_bfloat162 hh = __halves2bfloat162(ha, hb);
    __nv_bfloat162 ll = __halves2bfloat162(__float2bfloat16(ra), __float2bfloat16(rb));
    h = *reinterpret_cast<uint32_t*>(&hh);
    l = *reinterpret_cast<uint32_t*>(&ll);
}

// ================= splits =================
struct SplitA {                 // fp32 -> fp16 (A-side, unsplit)
    const float* src[2];
    __half* dst[2];
};
__global__ __launch_bounds__(256) void split_a(SplitA S) {
    const float* x = S.src[blockIdx.y];
    __half* d = S.dst[blockIdx.y];
    size_t i = ((size_t)blockIdx.x * 256 + threadIdx.x) * 4;
    float4 v = *(const float4*)(x + i);
    __half2 p0 = __floats2half2_rn(v.x, v.y);
    __half2 p1 = __floats2half2_rn(v.z, v.w);
    *(__half2*)(d + i)     = p0;
    *(__half2*)(d + i + 2) = p1;
}

struct SplitW {                 // fp32 -> fp16 hi + fp16 lo (weights)
    const float* src[6];
    __half* hi[6];
    __half* lo[6];
};
__global__ __launch_bounds__(256) void split_w(SplitW S) {
    const float* x = S.src[blockIdx.y];
    __half* hi = S.hi[blockIdx.y];
    __half* lo = S.lo[blockIdx.y];
    size_t i = ((size_t)blockIdx.x * 256 + threadIdx.x) * 4;
    float4 v = *(const float4*)(x + i);
    __half h0 = __float2half_rn(v.x), h1 = __float2half_rn(v.y);
    __half h2 = __float2half_rn(v.z), h3 = __float2half_rn(v.w);
    __half l0 = __float2half_rn(v.x - __half2float(h0));
    __half l1 = __float2half_rn(v.y - __half2float(h1));
    __half l2 = __float2half_rn(v.z - __half2float(h2));
    __half l3 = __float2half_rn(v.w - __half2float(h3));
    *(__half2*)(hi + i)     = __halves2half2(h0, h1);
    *(__half2*)(hi + i + 2) = __halves2half2(h2, h3);
    *(__half2*)(lo + i)     = __halves2half2(l0, l1);
    *(__half2*)(lo + i + 2) = __halves2half2(l2, l3);
}

// ================= fp16 2-pass mma.sync GEMM =================
// C = A * (Bh + Bl)^T per z. CTA 128x128, 8 warps @64x32, 3-stage cp.async,
// XOR-swizzled 64B rows, 72KB smem -> 2 CTAs/SM. Outputs bf16 hi/lo (for attn).
#define BM 128
#define BN 128
#define GT 256
#define TILE_B 8192                    // 128 rows * 64B
#define OFF_A  0
#define OFF_BH TILE_B
#define OFF_BL (2 * TILE_B)
#define STAGE_B (3 * TILE_B)           // 24576
#define NK 32
#define GEMM_SMEM (3 * STAGE_B)        // 73728

struct GemmTriple {
    const __half* A[3];
    const __half* Bh[3];
    const __half* Bl[3];
    __nv_bfloat16* Ch[3];
    __nv_bfloat16* Cl[3];
};

__device__ __forceinline__ void issue_stage(uint32_t sbase,
                                            const __half* Ap,
                                            const __half* Bhp, const __half* Blp,
                                            int kt, int tid) {
#pragma unroll
    for (int i = 0; i < 2; i++) {
        const int idx = tid + i * GT;                  // 0..511
        const int r = idx >> 2, c = idx & 3;
        const size_t goff = (size_t)r * 1024 + (size_t)kt * 32 + c * 8;
        const uint32_t soff = (uint32_t)(r * 64 + ((c ^ ((r >> 1) & 3)) * 16));
        CP_ASYNC16(sbase + OFF_A  + soff, (const char*)(Ap  + goff));
        CP_ASYNC16(sbase + OFF_BH + soff, (const char*)(Bhp + goff));
        CP_ASYNC16(sbase + OFF_BL + soff, (const char*)(Blp + goff));
    }
}

__global__ __launch_bounds__(GT, 2)
void gemm_qkv(GemmTriple P) {
    extern __shared__ char smc[];
    uint32_t sb = smem_u32(smc);
    const int tid = threadIdx.x;
    const int wid = tid >> 5, lane = tid & 31;
    const int z = blockIdx.z;
    const int m0 = blockIdx.y * BM;
    const int n0 = blockIdx.x * BN;
    const int wm = (wid & 1) * 64;
    const int wn = (wid >> 1) * 32;

    const __half* Ap  = P.A[z]  + (size_t)m0 * 1024;
    const __half* Bhp = P.Bh[z] + (size_t)n0 * 1024;
    const __half* Blp = P.Bl[z] + (size_t)n0 * 1024;

    const int lrow = (lane & 7) + ((lane >> 3) & 1) * 8;
    const int hi5 = (lane >> 4) & 1;   // k-half chunk bit

    float acc[4][4][4];
#pragma unroll
    for (int mt = 0; mt < 4; mt++)
#pragma unroll
        for (int nt = 0; nt < 4; nt++)
#pragma unroll
            for (int q = 0; q < 4; q++) acc[mt][nt][q] = 0.f;

    issue_stage(sb + 0 * STAGE_B, Ap, Bhp, Blp, 0, tid);
    CP_COMMIT();
    issue_stage(sb + 1 * STAGE_B, Ap, Bhp, Blp, 1, tid);
    CP_COMMIT();

    for (int kt = 0; kt < NK; kt++) {
        CP_WAIT1();            // stage kt landed
        __syncthreads();       // buffer (kt+2)%3 fully consumed (computed in kt-1)
        if (kt + 2 < NK)
            issue_stage(sb + ((kt + 2) % 3) * STAGE_B, Ap, Bhp, Blp, kt + 2, tid);
        CP_COMMIT();

        const uint32_t stb = sb + (kt % 3) * STAGE_B;
#pragma unroll
        for (int ks = 0; ks < 2; ks++) {
            uint32_t af[4][4];
#pragma unroll
            for (int mt = 0; mt < 4; mt++) {
                const int row = wm + mt * 16 + lrow;
                const uint32_t ro = (uint32_t)(row * 64 +
                    (((ks * 2 + hi5) ^ ((row >> 1) & 3)) * 16));
                LDSM_X4(af[mt][0], af[mt][1], af[mt][2], af[mt][3], stb + OFF_A + ro);
            }
#pragma unroll
            for (int g = 0; g < 2; g++) {   // two 16-col B groups -> nt = 2g, 2g+1
                const int row = wn + g * 16 + lrow;
                const uint32_t ro = (uint32_t)(row * 64 +
                    (((ks * 2 + hi5) ^ ((row >> 1) & 3)) * 16));
                uint32_t h0, h1, h2, h3, l0, l1, l2, l3;
                LDSM_X4(h0, h1, h2, h3, stb + OFF_BH + ro);
                LDSM_X4(l0, l1, l2, l3, stb + OFF_BL + ro);
                // pass 1: A * Bh (8 independent MMAs)
#pragma unroll
                for (int mt = 0; mt < 4; mt++) {
                    MMA_F16(acc[mt][2 * g + 0], af[mt], h0, h2);
                    MMA_F16(acc[mt][2 * g + 1], af[mt], h1, h3);
                }
                // pass 2: A * Bl
#pragma unroll
                for (int mt = 0; mt < 4; mt++) {
                    MMA_F16(acc[mt][2 * g + 0], af[mt], l0, l2);
                    MMA_F16(acc[mt][2 * g + 1], af[mt], l1, l3);
                }
            }
        }
    }

    __nv_bfloat16* Ch = P.Ch[z];
    __nv_bfloat16* Cl = P.Cl[z];
#pragma unroll
    for (int mt = 0; mt < 4; mt++) {
#pragma unroll
        for (int nt = 0; nt < 4; nt++) {
            int row = m0 + wm + mt * 16 + (lane >> 2);
            int col = n0 + wn + nt * 8 + (lane & 3) * 2;
            uint32_t h01, l01, h23, l23;
            pack_split(acc[mt][nt][0], acc[mt][nt][1], h01, l01);
            pack_split(acc[mt][nt][2], acc[mt][nt][3], h23, l23);
            *(uint32_t*)(Ch + (size_t)row * 1024 + col) = h01;
            *(uint32_t*)(Cl + (size_t)row * 1024 + col) = l01;
            *(uint32_t*)(Ch + (size_t)(row + 8) * 1024 + col) = h23;
            *(uint32_t*)(Cl + (size_t)(row + 8) * 1024 + col) = l23;
        }
    }
}

// ================= tensor-core flash attention (bf16 split, fp32 softmax) =================
#define APITCH 72
#define ATILE_B2 (64 * APITCH * 2)    // 9216
#define AQ_H 0
#define AQ_L ATILE_B2
#define AST(s, t) (2 * ATILE_B2 + (s) * (4 * ATILE_B2) + (t) * ATILE_B2)
#define ATTN_SMEM (2 * ATILE_B2 + 2 * 4 * ATILE_B2)   // 92160

__device__ __forceinline__ void attn_load_tile(uint32_t dst, const __nv_bfloat16* src, int tid) {
#pragma unroll
    for (int i = 0; i < 4; i++) {
        int idx = tid + i * 128;
        int r = idx >> 3, c = idx & 7;
        CP_ASYNC16(dst + (uint32_t)(r * 144 + c * 16),
                   (const char*)(src + (size_t)r * 1024 + c * 8));
    }
}

__global__ __launch_bounds__(128, 2)
void attn_mma(const __nv_bfloat16* __restrict__ Qh, const __nv_bfloat16* __restrict__ Ql,
              const __nv_bfloat16* __restrict__ Kh, const __nv_bfloat16* __restrict__ Kl,
              const __nv_bfloat16* __restrict__ Vh, const __nv_bfloat16* __restrict__ Vl,
              float* __restrict__ Of,
              __half* __restrict__ Oa,
              int causal) {
    extern __shared__ char smc[];
    uint32_t sb = smem_u32(smc);
    const int tid = threadIdx.x;
    const int wid = tid >> 5, lane = tid & 31;
    const int q0 = blockIdx.x * 64;
    const int h = blockIdx.y, b = blockIdx.z;
    const size_t rowbase = (size_t)(b * SEQ);
    const int colbase = h * HDIM;

    const int lrow = (lane & 7) + ((lane >> 3) & 1) * 8;
    const int lkof = ((lane >> 4) & 1) * 8;
    const int vrow_l = (lane & 7) + ((lane >> 4) & 1) * 8;
    const int vcol_l = ((lane >> 3) & 1) * 8;

    attn_load_tile(sb + AQ_H, Qh + (rowbase + q0) * 1024 + colbase, tid);
    attn_load_tile(sb + AQ_L, Ql + (rowbase + q0) * 1024 + colbase, tid);
    attn_load_tile(sb + AST(0, 0), Kh + rowbase * 1024 + colbase, tid);
    attn_load_tile(sb + AST(0, 1), Kl + rowbase * 1024 + colbase, tid);
    attn_load_tile(sb + AST(0, 2), Vh + rowbase * 1024 + colbase, tid);
    attn_load_tile(sb + AST(0, 3), Vl + rowbase * 1024 + colbase, tid);
    CP_COMMIT();

    const int njt = causal ? (blockIdx.x + 1) : (SEQ / 64);

    uint32_t qhf[4][4], qlf[4][4];
    float o[8][4];
#pragma unroll
    for (int nt = 0; nt < 8; nt++)
#pragma unroll
        for (int q = 0; q < 4; q++) o[nt][q] = 0.f;
    float m_[2] = {-1e30f, -1e30f}, l_[2] = {0.f, 0.f};

    for (int j = 0; j < njt; j++) {
        CP_WAIT0();
        __syncthreads();
        if (j + 1 < njt) {
            const size_t kb = (rowbase + (size_t)(j + 1) * 64) * 1024 + colbase;
            const int s = (j + 1) & 1;
            attn_load_tile(sb + AST(s, 0), Kh + kb, tid);
            attn_load_tile(sb + AST(s, 1), Kl + kb, tid);
            attn_load_tile(sb + AST(s, 2), Vh + kb, tid);
            attn_load_tile(sb + AST(s, 3), Vl + kb, tid);
            CP_COMMIT();
        }
        if (j == 0) {
#pragma unroll
            for (int kt = 0; kt < 4; kt++) {
                uint32_t ro = (uint32_t)((wid * 16 + lrow) * 144 + (kt * 16 + lkof) * 2);
                LDSM_X4(qhf[kt][0], qhf[kt][1], qhf[kt][2], qhf[kt][3], sb + AQ_H + ro);
                LDSM_X4(qlf[kt][0], qlf[kt][1], qlf[kt][2], qlf[kt][3], sb + AQ_L + ro);
            }
        }

        const uint32_t khb = sb + AST(j & 1, 0);
        const uint32_t klb = sb + AST(j & 1, 1);
        const uint32_t vhb = sb + AST(j & 1, 2);
        const uint32_t vlb = sb + AST(j & 1, 3);

        float s[8][4];
#pragma unroll
        for (int nt = 0; nt < 8; nt++)
#pragma unroll
            for (int q = 0; q < 4; q++) s[nt][q] = 0.f;
#pragma unroll
        for (int kt = 0; kt < 4; kt++) {
            uint32_t bh[8][2], bl[8][2];
#pragma unroll
            for (int g = 0; g < 4; g++) {
                uint32_t ro = (uint32_t)((g * 16 + lrow) * 144 + (kt * 16 + lkof) * 2);
                uint32_t r0, r1, r2, r3;
                LDSM_X4(r0, r1, r2, r3, khb + ro);
                bh[2 * g + 0][0] = r0; bh[2 * g + 0][1] = r2;
                bh[2 * g + 1][0] = r1; bh[2 * g + 1][1] = r3;
                LDSM_X4(r0, r1, r2, r3, klb + ro);
                bl[2 * g + 0][0] = r0; bl[2 * g + 0][1] = r2;
                bl[2 * g + 1][0] = r1; bl[2 * g + 1][1] = r3;
            }
#pragma unroll
            for (int nt = 0; nt < 8; nt++)
                MMA_BF16(s[nt], qhf[kt], bh[nt][0], bh[nt][1]);
#pragma unroll
            for (int nt = 0; nt < 8; nt++)
                MMA_BF16(s[nt], qhf[kt], bl[nt][0], bl[nt][1]);
#pragma unroll
            for (int nt = 0; nt < 8; nt++)
                MMA_BF16(s[nt], qlf[kt], bh[nt][0], bh[nt][1]);
        }

#pragma unroll
        for (int nt = 0; nt < 8; nt++)
#pragma unroll
            for (int q = 0; q < 4; q++) s[nt][q] *= 0.125f;
        if (causal && j == njt - 1) {
            const int r0l = wid * 16 + (lane >> 2), r1l = r0l + 8;
#pragma unroll
            for (int nt = 0; nt < 8; nt++) {
                const int c0 = nt * 8 + (lane & 3) * 2;
                if (c0 > r0l)     s[nt][0] = -1e9f;
                if (c0 + 1 > r0l) s[nt][1] = -1e9f;
                if (c0 > r1l)     s[nt][2] = -1e9f;
                if (c0 + 1 > r1l) s[nt][3] = -1e9f;
            }
        }

        float mx0 = -1e30f, mx1 = -1e30f;
#pragma unroll
        for (int nt = 0; nt < 8; nt++) {
            mx0 = fmaxf(mx0, fmaxf(s[nt][0], s[nt][1]));
            mx1 = fmaxf(mx1, fmaxf(s[nt][2], s[nt][3]));
        }
        mx0 = fmaxf(mx0, __shfl_xor_sync(0xffffffffu, mx0, 1));
        mx0 = fmaxf(mx0, __shfl_xor_sync(0xffffffffu, mx0, 2));
        mx1 = fmaxf(mx1, __shfl_xor_sync(0xffffffffu, mx1, 1));
        mx1 = fmaxf(mx1, __shfl_xor_sync(0xffffffffu, mx1, 2));
        const float mn0 = fmaxf(m_[0], mx0), mn1 = fmaxf(m_[1], mx1);
        const float f0 = __expf(m_[0] - mn0), f1 = __expf(m_[1] - mn1);
        m_[0] = mn0; m_[1] = mn1;
        float rs0 = 0.f, rs1 = 0.f;
#pragma unroll
        for (int nt = 0; nt < 8; nt++) {
            s[nt][0] = __expf(s[nt][0] - mn0);
            s[nt][1] = __expf(s[nt][1] - mn0);
            s[nt][2] = __expf(s[nt][2] - mn1);
            s[nt][3] = __expf(s[nt][3] - mn1);
            rs0 += s[nt][0] + s[nt][1];
            rs1 += s[nt][2] + s[nt][3];
        }
        rs0 += __shfl_xor_sync(0xffffffffu, rs0, 1);
        rs0 += __shfl_xor_sync(0xffffffffu, rs0, 2);
        rs1 += __shfl_xor_sync(0xffffffffu, rs1, 1);
        rs1 += __shfl_xor_sync(0xffffffffu, rs1, 2);
        l_[0] = l_[0] * f0 + rs0;
        l_[1] = l_[1] * f1 + rs1;
#pragma unroll
        for (int nt = 0; nt < 8; nt++) {
            o[nt][0] *= f0; o[nt][1] *= f0; o[nt][2] *= f1; o[nt][3] *= f1;
        }

        uint32_t ph[4][4], pl[4][4];
#pragma unroll
        for (int kt = 0; kt < 4; kt++) {
            pack_split(s[2 * kt][0],     s[2 * kt][1],     ph[kt][0], pl[kt][0]);
            pack_split(s[2 * kt][2],     s[2 * kt][3],     ph[kt][1], pl[kt][1]);
            pack_split(s[2 * kt + 1][0], s[2 * kt + 1][1], ph[kt][2], pl[kt][2]);
            pack_split(s[2 * kt + 1][2], s[2 * kt + 1][3], ph[kt][3], pl[kt][3]);
        }

#pragma unroll
        for (int kt = 0; kt < 4; kt++) {
            const uint32_t vro = (uint32_t)((kt * 16 + vrow_l) * 144);
            uint32_t bh[8][2], bl[8][2];
#pragma unroll
            for (int g = 0; g < 4; g++) {
                uint32_t ro = vro + (uint32_t)((g * 16 + vcol_l) * 2);
                uint32_t r0, r1, r2, r3;
                LDSM_X4_T(r0, r1, r2, r3, vhb + ro);
                bh[2 * g + 0][0] = r0; bh[2 * g + 0][1] = r2;
                bh[2 * g + 1][0] = r1; bh[2 * g + 1][1] = r3;
                LDSM_X4_T(r0, r1, r2, r3, vlb + ro);
                bl[2 * g + 0][0] = r0; bl[2 * g + 0][1] = r2;
                bl[2 * g + 1][0] = r1; bl[2 * g + 1][1] = r3;
            }
#pragma unroll
            for (int nt = 0; nt < 8; nt++)
                MMA_BF16(o[nt], ph[kt], bh[nt][0], bh[nt][1]);
#pragma unroll
            for (int nt = 0; nt < 8; nt++)
                MMA_BF16(o[nt], ph[kt], bl[nt][0], bl[nt][1]);
#pragma unroll
            for (int nt = 0; nt < 8; nt++)
                MMA_BF16(o[nt], pl[kt], bh[nt][0], bh[nt][1]);
        }
    }

    const float inv0 = 1.f / l_[0], inv1 = 1.f / l_[1];
    const size_t row0 = rowbase + q0 + wid * 16 + (lane >> 2);
    const int col = colbase + (lane & 3) * 2;
    if (Of) {
#pragma unroll
        for (int nt = 0; nt < 8; nt++) {
            *(float2*)(Of + row0 * 1024 + col + nt * 8) =
                make_float2(o[nt][0] * inv0, o[nt][1] * inv0);
            *(float2*)(Of + (row0 + 8) * 1024 + col + nt * 8) =
                make_float2(o[nt][2] * inv1, o[nt][3] * inv1);
        }
    } else {
#pragma unroll
        for (int nt = 0; nt < 8; nt++) {
            *(__half2*)(Oa + row0 * 1024 + col + nt * 8) =
                __floats2half2_rn(o[nt][0] * inv0, o[nt][1] * inv0);
            *(__half2*)(Oa + (row0 + 8) * 1024 + col + nt * 8) =
                __floats2half2_rn(o[nt][2] * inv1, o[nt][3] * inv1);
        }
    }
}

// ================= launch =================
extern "C" void kernel_launch(void* const* d_in, const int* in_sizes, int n_in,
                              void* d_out, int out_size) {
    const float* x   = (const float*)d_in[0];
    const float* enc = (const float*)d_in[1];
    const float* w[6] = {(const float*)d_in[4], (const float*)d_in[5],
                         (const float*)d_in[6], (const float*)d_in[7],
                         (const float*)d_in[8], (const float*)d_in[9]};
    float* out = (float*)d_out;

    __nv_bfloat16 *qh, *ql, *kh, *kl, *vh, *vl, *kh2, *kl2, *vh2, *vl2;
    __half *xa, *ea, *sa, *wh, *wl;
    cudaGetSymbolAddress((void**)&qh, g_qh);
    cudaGetSymbolAddress((void**)&ql, g_ql);
    cudaGetSymbolAddress((void**)&kh, g_kh);
    cudaGetSymbolAddress((void**)&kl, g_kl);
    cudaGetSymbolAddress((void**)&vh, g_vh);
    cudaGetSymbolAddress((void**)&vl, g_vl);
    cudaGetSymbolAddress((void**)&kh2, g_kh2);
    cudaGetSymbolAddress((void**)&kl2, g_kl2);
    cudaGetSymbolAddress((void**)&vh2, g_vh2);
    cudaGetSymbolAddress((void**)&vl2, g_vl2);
    cudaGetSymbolAddress((void**)&xa, g_xa);
    cudaGetSymbolAddress((void**)&ea, g_ea);
    cudaGetSymbolAddress((void**)&sa, g_sa);
    cudaGetSymbolAddress((void**)&wh, g_w6h);
    cudaGetSymbolAddress((void**)&wl, g_w6l);

    cudaFuncSetAttribute(gemm_qkv, cudaFuncAttributeMaxDynamicSharedMemorySize, GEMM_SMEM);
    cudaFuncSetAttribute(attn_mma, cudaFuncAttributeMaxDynamicSharedMemorySize, ATTN_SMEM);

    static cudaStream_t s1 = nullptr;
    static cudaEvent_t ev_fork = nullptr, ev_kv = nullptr;
    if (!s1) {
        cudaStreamCreateWithFlags(&s1, cudaStreamNonBlocking);
        cudaEventCreateWithFlags(&ev_fork, cudaEventDisableTiming);
        cudaEventCreateWithFlags(&ev_kv, cudaEventDisableTiming);
    }

    const size_t WSZ = (size_t)DMODEL * DMODEL;
    dim3 gg3(DMODEL / BN, MTOT / BM, 3);                 // (8, 32, 3)
    dim3 gg2(DMODEL / BN, MTOT / BM, 2);                 // cross K,V
    dim3 gg1(DMODEL / BN, MTOT / BM, 1);                 // cross Q
    dim3 ga(SEQ / 64, NHEAD, BATCH);                     // (16, 16, 4)

    // ---- splits ----
    SplitA Sa = {};
    Sa.src[0] = x;   Sa.dst[0] = xa;
    Sa.src[1] = enc; Sa.dst[1] = ea;
    split_a<<<dim3((MTOT * DMODEL) / (256 * 4), 2), 256>>>(Sa);

    SplitW Sw = {};
    for (int i = 0; i < 6; i++) {
        Sw.src[i] = w[i]; Sw.hi[i] = wh + i * WSZ; Sw.lo[i] = wl + i * WSZ;
    }
    split_w<<<dim3((int)(WSZ / (256 * 4)), 6), 256>>>(Sw);

    // ---- fork: s1 runs cross-K/V GEMM concurrently with self block ----
    cudaEventRecord(ev_fork, 0);
    cudaStreamWaitEvent(s1, ev_fork, 0);

    GemmTriple Pkv;
    Pkv.A[0] = ea; Pkv.A[1] = ea;
    Pkv.Bh[0] = wh + 4 * WSZ; Pkv.Bl[0] = wl + 4 * WSZ;
    Pkv.Bh[1] = wh + 5 * WSZ; Pkv.Bl[1] = wl + 5 * WSZ;
    Pkv.Ch[0] = kh2; Pkv.Cl[0] = kl2;
    Pkv.Ch[1] = vh2; Pkv.Cl[1] = vl2;
    gemm_qkv<<<gg2, GT, GEMM_SMEM, s1>>>(Pkv);
    cudaEventRecord(ev_kv, s1);

    // ---- self block (default stream) ----
    GemmTriple Ps;
    for (int zi = 0; zi < 3; zi++) {
        Ps.A[zi] = xa;
        Ps.Bh[zi] = wh + zi * WSZ; Ps.Bl[zi] = wl + zi * WSZ;
    }
    Ps.Ch[0] = qh; Ps.Cl[0] = ql;
    Ps.Ch[1] = kh; Ps.Cl[1] = kl;
    Ps.Ch[2] = vh; Ps.Cl[2] = vl;
    gemm_qkv<<<gg3, GT, GEMM_SMEM>>>(Ps);
    attn_mma<<<ga, 128, ATTN_SMEM>>>(qh, ql, kh, kl, vh, vl, nullptr, sa, 1);

    // ---- cross Q GEMM (A = attn_self output, fp16) ----
    GemmTriple Pq;
    Pq.A[0] = sa;
    Pq.Bh[0] = wh + 3 * WSZ; Pq.Bl[0] = wl + 3 * WSZ;
    Pq.Ch[0] = qh; Pq.Cl[0] = ql;
    gemm_qkv<<<gg1, GT, GEMM_SMEM>>>(Pq);

    // ---- join, then cross attention ----
    cudaStreamWaitEvent(0, ev_kv, 0);
    attn_mma<<<ga, 128, ATTN_SMEM>>>(qh, ql, kh2, kl2, vh2, vl2, out, nullptr, 0);
}

// round 17
// speedup vs baseline: 1.4875x; 1.0666x over previous
#include <cuda_runtime.h>
#include <cuda_fp16.h>
#include <cstdint>

// DecoderBlock: self-MHA (causal) -> cross-MHA (no mask).
// B=4, S=1024, D=1024, H=16, DK=64.
// R17: everything fp16. GEMMs: C = fp16(A)*(Bh+Bl), 2-pass. Attention:
//      Q,K,V fp16 hi/lo; QK^T 3-pass (more accurate than bf16 split);
//      PV 2-pass with P fp16 UNSPLIT (P in [0,1]). 5 passes vs 6.
//      Stream overlap (cross-KV gemm || self block) kept from R16.

#define SEQ    1024
#define DMODEL 1024
#define NHEAD  16
#define HDIM   64
#define BATCH  4
#define MTOT   (BATCH * SEQ)   // 4096

// ---------------- scratch ----------------
__device__ __half g_qh[(size_t)MTOT * DMODEL];
__device__ __half g_ql[(size_t)MTOT * DMODEL];
__device__ __half g_kh[(size_t)MTOT * DMODEL];
__device__ __half g_kl[(size_t)MTOT * DMODEL];
__device__ __half g_vh[(size_t)MTOT * DMODEL];
__device__ __half g_vl[(size_t)MTOT * DMODEL];
__device__ __half g_kh2[(size_t)MTOT * DMODEL];
__device__ __half g_kl2[(size_t)MTOT * DMODEL];
__device__ __half g_vh2[(size_t)MTOT * DMODEL];
__device__ __half g_vl2[(size_t)MTOT * DMODEL];
__device__ __half g_xa[(size_t)MTOT * DMODEL];           // fp16(x)
__device__ __half g_ea[(size_t)MTOT * DMODEL];           // fp16(enc)
__device__ __half g_sa[(size_t)MTOT * DMODEL];           // fp16(attn_self out)
__device__ __half g_w6h[6 * (size_t)DMODEL * DMODEL];
__device__ __half g_w6l[6 * (size_t)DMODEL * DMODEL];

// ================= PTX helpers =================
__device__ __forceinline__ uint32_t smem_u32(const void* p) {
    uint32_t a;
    asm("{ .reg .u64 t; cvta.to.shared.u64 t, %1; cvt.u32.u64 %0, t; }" : "=r"(a) : "l"(p));
    return a;
}
#define CP_ASYNC16(dst, src) asm volatile("cp.async.cg.shared.global [%0], [%1], 16;" :: "r"(dst), "l"(src))
#define CP_COMMIT()  asm volatile("cp.async.commit_group;" ::: "memory")
#define CP_WAIT1()   asm volatile("cp.async.wait_group 1;" ::: "memory")
#define CP_WAIT0()   asm volatile("cp.async.wait_group 0;" ::: "memory")

#define LDSM_X4(r0, r1, r2, r3, addr) \
    asm volatile("ldmatrix.sync.aligned.m8n8.x4.shared.b16 {%0,%1,%2,%3}, [%4];" \
                 : "=r"(r0), "=r"(r1), "=r"(r2), "=r"(r3) : "r"(addr))
#define LDSM_X4_T(r0, r1, r2, r3, addr) \
    asm volatile("ldmatrix.sync.aligned.m8n8.x4.trans.shared.b16 {%0,%1,%2,%3}, [%4];" \
                 : "=r"(r0), "=r"(r1), "=r"(r2), "=r"(r3) : "r"(addr))

#define MMA_F16(c, a, b0v, b1v) \
    asm volatile("mma.sync.aligned.m16n8k16.row.col.f32.f16.f16.f32 " \
                 "{%0,%1,%2,%3}, {%4,%5,%6,%7}, {%8,%9}, {%0,%1,%2,%3};" \
                 : "+f"((c)[0]), "+f"((c)[1]), "+f"((c)[2]), "+f"((c)[3]) \
                 : "r"((a)[0]), "r"((a)[1]), "r"((a)[2]), "r"((a)[3]), \
                   "r"(b0v), "r"(b1v))

__device__ __forceinline__ void pack_split_h(float a, float b, uint32_t& h, uint32_t& l) {
    __half ha = __float2half_rn(a), hb = __float2half_rn(b);
    float ra = a - __half2float(ha), rb = b - __half2float(hb);
    __half2 hh = __halves2half2(ha, hb);
    __half2 ll = __halves2half2(__float2half_rn(ra), __float2half_rn(rb));
    h = *reinterpret_cast<uint32_t*>(&hh);
    l = *reinterpret_cast<uint32_t*>(&ll);
}
__device__ __forceinline__ uint32_t pack_h2(float a, float b) {
    __half2 p = __floats2half2_rn(a, b);
    return *reinterpret_cast<uint32_t*>(&p);
}

// ================= splits =================
struct SplitA {                 // fp32 -> fp16 (A-side, unsplit)
    const float* src[2];
    __half* dst[2];
};
__global__ __launch_bounds__(256) void split_a(SplitA S) {
    const float* x = S.src[blockIdx.y];
    __half* d = S.dst[blockIdx.y];
    size_t i = ((size_t)blockIdx.x * 256 + threadIdx.x) * 4;
    float4 v = *(const float4*)(x + i);
    *(__half2*)(d + i)     = __floats2half2_rn(v.x, v.y);
    *(__half2*)(d + i + 2) = __floats2half2_rn(v.z, v.w);
}

struct SplitW {                 // fp32 -> fp16 hi + fp16 lo
    const float* src[6];
    __half* hi[6];
    __half* lo[6];
};
__global__ __launch_bounds__(256) void split_w(SplitW S) {
    const float* x = S.src[blockIdx.y];
    __half* hi = S.hi[blockIdx.y];
    __half* lo = S.lo[blockIdx.y];
    size_t i = ((size_t)blockIdx.x * 256 + threadIdx.x) * 4;
    float4 v = *(const float4*)(x + i);
    uint32_t h0, l0, h1, l1;
    pack_split_h(v.x, v.y, h0, l0);
    pack_split_h(v.z, v.w, h1, l1);
    *(uint32_t*)(hi + i)     = h0; *(uint32_t*)(hi + i + 2) = h1;
    *(uint32_t*)(lo + i)     = l0; *(uint32_t*)(lo + i + 2) = l1;
}

// ================= fp16 2-pass mma.sync GEMM =================
// C = A * (Bh + Bl)^T per z. CTA 128x128, 8 warps @64x32, 3-stage cp.async,
// XOR-swizzled 64B rows, 72KB smem -> 2 CTAs/SM. Outputs fp16 hi/lo.
#define BM 128
#define BN 128
#define GT 256
#define TILE_B 8192                    // 128 rows * 64B
#define OFF_A  0
#define OFF_BH TILE_B
#define OFF_BL (2 * TILE_B)
#define STAGE_B (3 * TILE_B)           // 24576
#define NK 32
#define GEMM_SMEM (3 * STAGE_B)        // 73728

struct GemmTriple {
    const __half* A[3];
    const __half* Bh[3];
    const __half* Bl[3];
    __half* Ch[3];
    __half* Cl[3];
};

__device__ __forceinline__ void issue_stage(uint32_t sbase,
                                            const __half* Ap,
                                            const __half* Bhp, const __half* Blp,
                                            int kt, int tid) {
#pragma unroll
    for (int i = 0; i < 2; i++) {
        const int idx = tid + i * GT;                  // 0..511
        const int r = idx >> 2, c = idx & 3;
        const size_t goff = (size_t)r * 1024 + (size_t)kt * 32 + c * 8;
        const uint32_t soff = (uint32_t)(r * 64 + ((c ^ ((r >> 1) & 3)) * 16));
        CP_ASYNC16(sbase + OFF_A  + soff, (const char*)(Ap  + goff));
        CP_ASYNC16(sbase + OFF_BH + soff, (const char*)(Bhp + goff));
        CP_ASYNC16(sbase + OFF_BL + soff, (const char*)(Blp + goff));
    }
}

__global__ __launch_bounds__(GT, 2)
void gemm_qkv(GemmTriple P) {
    extern __shared__ char smc[];
    uint32_t sb = smem_u32(smc);
    const int tid = threadIdx.x;
    const int wid = tid >> 5, lane = tid & 31;
    const int z = blockIdx.z;
    const int m0 = blockIdx.y * BM;
    const int n0 = blockIdx.x * BN;
    const int wm = (wid & 1) * 64;
    const int wn = (wid >> 1) * 32;

    const __half* Ap  = P.A[z]  + (size_t)m0 * 1024;
    const __half* Bhp = P.Bh[z] + (size_t)n0 * 1024;
    const __half* Blp = P.Bl[z] + (size_t)n0 * 1024;

    const int lrow = (lane & 7) + ((lane >> 3) & 1) * 8;
    const int hi5 = (lane >> 4) & 1;

    float acc[4][4][4];
#pragma unroll
    for (int mt = 0; mt < 4; mt++)
#pragma unroll
        for (int nt = 0; nt < 4; nt++)
#pragma unroll
            for (int q = 0; q < 4; q++) acc[mt][nt][q] = 0.f;

    issue_stage(sb + 0 * STAGE_B, Ap, Bhp, Blp, 0, tid);
    CP_COMMIT();
    issue_stage(sb + 1 * STAGE_B, Ap, Bhp, Blp, 1, tid);
    CP_COMMIT();

    for (int kt = 0; kt < NK; kt++) {
        CP_WAIT1();
        __syncthreads();
        if (kt + 2 < NK)
            issue_stage(sb + ((kt + 2) % 3) * STAGE_B, Ap, Bhp, Blp, kt + 2, tid);
        CP_COMMIT();

        const uint32_t stb = sb + (kt % 3) * STAGE_B;
#pragma unroll
        for (int ks = 0; ks < 2; ks++) {
            uint32_t af[4][4];
#pragma unroll
            for (int mt = 0; mt < 4; mt++) {
                const int row = wm + mt * 16 + lrow;
                const uint32_t ro = (uint32_t)(row * 64 +
                    (((ks * 2 + hi5) ^ ((row >> 1) & 3)) * 16));
                LDSM_X4(af[mt][0], af[mt][1], af[mt][2], af[mt][3], stb + OFF_A + ro);
            }
#pragma unroll
            for (int g = 0; g < 2; g++) {
                const int row = wn + g * 16 + lrow;
                const uint32_t ro = (uint32_t)(row * 64 +
                    (((ks * 2 + hi5) ^ ((row >> 1) & 3)) * 16));
                uint32_t h0, h1, h2, h3, l0, l1, l2, l3;
                LDSM_X4(h0, h1, h2, h3, stb + OFF_BH + ro);
                LDSM_X4(l0, l1, l2, l3, stb + OFF_BL + ro);
#pragma unroll
                for (int mt = 0; mt < 4; mt++) {
                    MMA_F16(acc[mt][2 * g + 0], af[mt], h0, h2);
                    MMA_F16(acc[mt][2 * g + 1], af[mt], h1, h3);
                }
#pragma unroll
                for (int mt = 0; mt < 4; mt++) {
                    MMA_F16(acc[mt][2 * g + 0], af[mt], l0, l2);
                    MMA_F16(acc[mt][2 * g + 1], af[mt], l1, l3);
                }
            }
        }
    }

    __half* Ch = P.Ch[z];
    __half* Cl = P.Cl[z];
#pragma unroll
    for (int mt = 0; mt < 4; mt++) {
#pragma unroll
        for (int nt = 0; nt < 4; nt++) {
            int row = m0 + wm + mt * 16 + (lane >> 2);
            int col = n0 + wn + nt * 8 + (lane & 3) * 2;
            uint32_t h01, l01, h23, l23;
            pack_split_h(acc[mt][nt][0], acc[mt][nt][1], h01, l01);
            pack_split_h(acc[mt][nt][2], acc[mt][nt][3], h23, l23);
            *(uint32_t*)(Ch + (size_t)row * 1024 + col) = h01;
            *(uint32_t*)(Cl + (size_t)row * 1024 + col) = l01;
            *(uint32_t*)(Ch + (size_t)(row + 8) * 1024 + col) = h23;
            *(uint32_t*)(Cl + (size_t)(row + 8) * 1024 + col) = l23;
        }
    }
}

// ================= tensor-core flash attention (fp16, 5 MMA passes) =================
// QK^T: 3-pass (Qh,Ql x Kh,Kl minus lo*lo). PV: 2-pass, P fp16 unsplit.
#define APITCH 72
#define ATILE_B2 (64 * APITCH * 2)    // 9216
#define AQ_H 0
#define AQ_L ATILE_B2
#define AST(s, t) (2 * ATILE_B2 + (s) * (4 * ATILE_B2) + (t) * ATILE_B2)
#define ATTN_SMEM (2 * ATILE_B2 + 2 * 4 * ATILE_B2)   // 92160

__device__ __forceinline__ void attn_load_tile(uint32_t dst, const __half* src, int tid) {
#pragma unroll
    for (int i = 0; i < 4; i++) {
        int idx = tid + i * 128;
        int r = idx >> 3, c = idx & 7;
        CP_ASYNC16(dst + (uint32_t)(r * 144 + c * 16),
                   (const char*)(src + (size_t)r * 1024 + c * 8));
    }
}

__global__ __launch_bounds__(128, 2)
void attn_mma(const __half* __restrict__ Qh, const __half* __restrict__ Ql,
              const __half* __restrict__ Kh, const __half* __restrict__ Kl,
              const __half* __restrict__ Vh, const __half* __restrict__ Vl,
              float* __restrict__ Of,
              __half* __restrict__ Oa,
              int causal) {
    extern __shared__ char smc[];
    uint32_t sb = smem_u32(smc);
    const int tid = threadIdx.x;
    const int wid = tid >> 5, lane = tid & 31;
    const int q0 = blockIdx.x * 64;
    const int h = blockIdx.y, b = blockIdx.z;
    const size_t rowbase = (size_t)(b * SEQ);
    const int colbase = h * HDIM;

    const int lrow = (lane & 7) + ((lane >> 3) & 1) * 8;
    const int lkof = ((lane >> 4) & 1) * 8;
    const int vrow_l = (lane & 7) + ((lane >> 4) & 1) * 8;
    const int vcol_l = ((lane >> 3) & 1) * 8;

    attn_load_tile(sb + AQ_H, Qh + (rowbase + q0) * 1024 + colbase, tid);
    attn_load_tile(sb + AQ_L, Ql + (rowbase + q0) * 1024 + colbase, tid);
    attn_load_tile(sb + AST(0, 0), Kh + rowbase * 1024 + colbase, tid);
    attn_load_tile(sb + AST(0, 1), Kl + rowbase * 1024 + colbase, tid);
    attn_load_tile(sb + AST(0, 2), Vh + rowbase * 1024 + colbase, tid);
    attn_load_tile(sb + AST(0, 3), Vl + rowbase * 1024 + colbase, tid);
    CP_COMMIT();

    const int njt = causal ? (blockIdx.x + 1) : (SEQ / 64);

    uint32_t qhf[4][4], qlf[4][4];
    float o[8][4];
#pragma unroll
    for (int nt = 0; nt < 8; nt++)
#pragma unroll
        for (int q = 0; q < 4; q++) o[nt][q] = 0.f;
    float m_[2] = {-1e30f, -1e30f}, l_[2] = {0.f, 0.f};

    for (int j = 0; j < njt; j++) {
        CP_WAIT0();
        __syncthreads();
        if (j + 1 < njt) {
            const size_t kb = (rowbase + (size_t)(j + 1) * 64) * 1024 + colbase;
            const int s = (j + 1) & 1;
            attn_load_tile(sb + AST(s, 0), Kh + kb, tid);
            attn_load_tile(sb + AST(s, 1), Kl + kb, tid);
            attn_load_tile(sb + AST(s, 2), Vh + kb, tid);
            attn_load_tile(sb + AST(s, 3), Vl + kb, tid);
            CP_COMMIT();
        }
        if (j == 0) {
#pragma unroll
            for (int kt = 0; kt < 4; kt++) {
                uint32_t ro = (uint32_t)((wid * 16 + lrow) * 144 + (kt * 16 + lkof) * 2);
                LDSM_X4(qhf[kt][0], qhf[kt][1], qhf[kt][2], qhf[kt][3], sb + AQ_H + ro);
                LDSM_X4(qlf[kt][0], qlf[kt][1], qlf[kt][2], qlf[kt][3], sb + AQ_L + ro);
            }
        }

        const uint32_t khb = sb + AST(j & 1, 0);
        const uint32_t klb = sb + AST(j & 1, 1);
        const uint32_t vhb = sb + AST(j & 1, 2);
        const uint32_t vlb = sb + AST(j & 1, 3);

        float s[8][4];
#pragma unroll
        for (int nt = 0; nt < 8; nt++)
#pragma unroll
            for (int q = 0; q < 4; q++) s[nt][q] = 0.f;
#pragma unroll
        for (int kt = 0; kt < 4; kt++) {
            uint32_t bh[8][2], bl[8][2];
#pragma unroll
            for (int g = 0; g < 4; g++) {
                uint32_t ro = (uint32_t)((g * 16 + lrow) * 144 + (kt * 16 + lkof) * 2);
                uint32_t r0, r1, r2, r3;
                LDSM_X4(r0, r1, r2, r3, khb + ro);
                bh[2 * g + 0][0] = r0; bh[2 * g + 0][1] = r2;
                bh[2 * g + 1][0] = r1; bh[2 * g + 1][1] = r3;
                LDSM_X4(r0, r1, r2, r3, klb + ro);
                bl[2 * g + 0][0] = r0; bl[2 * g + 0][1] = r2;
                bl[2 * g + 1][0] = r1; bl[2 * g + 1][1] = r3;
            }
#pragma unroll
            for (int nt = 0; nt < 8; nt++)
                MMA_F16(s[nt], qhf[kt], bh[nt][0], bh[nt][1]);
#pragma unroll
            for (int nt = 0; nt < 8; nt++)
                MMA_F16(s[nt], qhf[kt], bl[nt][0], bl[nt][1]);
#pragma unroll
            for (int nt = 0; nt < 8; nt++)
                MMA_F16(s[nt], qlf[kt], bh[nt][0], bh[nt][1]);
        }

#pragma unroll
        for (int nt = 0; nt < 8; nt++)
#pragma unroll
            for (int q = 0; q < 4; q++) s[nt][q] *= 0.125f;
        if (causal && j == njt - 1) {
            const int r0l = wid * 16 + (lane >> 2), r1l = r0l + 8;
#pragma unroll
            for (int nt = 0; nt < 8; nt++) {
                const int c0 = nt * 8 + (lane & 3) * 2;
                if (c0 > r0l)     s[nt][0] = -1e9f;
                if (c0 + 1 > r0l) s[nt][1] = -1e9f;
                if (c0 > r1l)     s[nt][2] = -1e9f;
                if (c0 + 1 > r1l) s[nt][3] = -1e9f;
            }
        }

        float mx0 = -1e30f, mx1 = -1e30f;
#pragma unroll
        for (int nt = 0; nt < 8; nt++) {
            mx0 = fmaxf(mx0, fmaxf(s[nt][0], s[nt][1]));
            mx1 = fmaxf(mx1, fmaxf(s[nt][2], s[nt][3]));
        }
        mx0 = fmaxf(mx0, __shfl_xor_sync(0xffffffffu, mx0, 1));
        mx0 = fmaxf(mx0, __shfl_xor_sync(0xffffffffu, mx0, 2));
        mx1 = fmaxf(mx1, __shfl_xor_sync(0xffffffffu, mx1, 1));
        mx1 = fmaxf(mx1, __shfl_xor_sync(0xffffffffu, mx1, 2));
        const float mn0 = fmaxf(m_[0], mx0), mn1 = fmaxf(m_[1], mx1);
        const float f0 = __expf(m_[0] - mn0), f1 = __expf(m_[1] - mn1);
        m_[0] = mn0; m_[1] = mn1;
        float rs0 = 0.f, rs1 = 0.f;
#pragma unroll
        for (int nt = 0; nt < 8; nt++) {
            s[nt][0] = __expf(s[nt][0] - mn0);
            s[nt][1] = __expf(s[nt][1] - mn0);
            s[nt][2] = __expf(s[nt][2] - mn1);
            s[nt][3] = __expf(s[nt][3] - mn1);
            rs0 += s[nt][0] + s[nt][1];
            rs1 += s[nt][2] + s[nt][3];
        }
        rs0 += __shfl_xor_sync(0xffffffffu, rs0, 1);
        rs0 += __shfl_xor_sync(0xffffffffu, rs0, 2);
        rs1 += __shfl_xor_sync(0xffffffffu, rs1, 1);
        rs1 += __shfl_xor_sync(0xffffffffu, rs1, 2);
        l_[0] = l_[0] * f0 + rs0;
        l_[1] = l_[1] * f1 + rs1;
#pragma unroll
        for (int nt = 0; nt < 8; nt++) {
            o[nt][0] *= f0; o[nt][1] *= f0; o[nt][2] *= f1; o[nt][3] *= f1;
        }

        // P as fp16 a-frags, UNSPLIT (P in [0,1] -> 2.4e-4 relative rounding)
        uint32_t ph[4][4];
#pragma unroll
        for (int kt = 0; kt < 4; kt++) {
            ph[kt][0] = pack_h2(s[2 * kt][0],     s[2 * kt][1]);
            ph[kt][1] = pack_h2(s[2 * kt][2],     s[2 * kt][3]);
            ph[kt][2] = pack_h2(s[2 * kt + 1][0], s[2 * kt + 1][1]);
            ph[kt][3] = pack_h2(s[2 * kt + 1][2], s[2 * kt + 1][3]);
        }

        // PV: 2 passes (P x Vh, P x Vl)
#pragma unroll
        for (int kt = 0; kt < 4; kt++) {
            const uint32_t vro = (uint32_t)((kt * 16 + vrow_l) * 144);
            uint32_t bh[8][2], bl[8][2];
#pragma unroll
            for (int g = 0; g < 4; g++) {
                uint32_t ro = vro + (uint32_t)((g * 16 + vcol_l) * 2);
                uint32_t r0, r1, r2, r3;
                LDSM_X4_T(r0, r1, r2, r3, vhb + ro);
                bh[2 * g + 0][0] = r0; bh[2 * g + 0][1] = r2;
                bh[2 * g + 1][0] = r1; bh[2 * g + 1][1] = r3;
                LDSM_X4_T(r0, r1, r2, r3, vlb + ro);
                bl[2 * g + 0][0] = r0; bl[2 * g + 0][1] = r2;
                bl[2 * g + 1][0] = r1; bl[2 * g + 1][1] = r3;
            }
#pragma unroll
            for (int nt = 0; nt < 8; nt++)
                MMA_F16(o[nt], ph[kt], bh[nt][0], bh[nt][1]);
#pragma unroll
            for (int nt = 0; nt < 8; nt++)
                MMA_F16(o[nt], ph[kt], bl[nt][0], bl[nt][1]);
        }
    }

    const float inv0 = 1.f / l_[0], inv1 = 1.f / l_[1];
    const size_t row0 = rowbase + q0 + wid * 16 + (lane >> 2);
    const int col = colbase + (lane & 3) * 2;
    if (Of) {
#pragma unroll
        for (int nt = 0; nt < 8; nt++) {
            *(float2*)(Of + row0 * 1024 + col + nt * 8) =
                make_float2(o[nt][0] * inv0, o[nt][1] * inv0);
            *(float2*)(Of + (row0 + 8) * 1024 + col + nt * 8) =
                make_float2(o[nt][2] * inv1, o[nt][3] * inv1);
        }
    } else {
#pragma unroll
        for (int nt = 0; nt < 8; nt++) {
            *(__half2*)(Oa + row0 * 1024 + col + nt * 8) =
                __floats2half2_rn(o[nt][0] * inv0, o[nt][1] * inv0);
            *(__half2*)(Oa + (row0 + 8) * 1024 + col + nt * 8) =
                __floats2half2_rn(o[nt][2] * inv1, o[nt][3] * inv1);
        }
    }
}

// ================= launch =================
extern "C" void kernel_launch(void* const* d_in, const int* in_sizes, int n_in,
                              void* d_out, int out_size) {
    const float* x   = (const float*)d_in[0];
    const float* enc = (const float*)d_in[1];
    const float* w[6] = {(const float*)d_in[4], (const float*)d_in[5],
                         (const float*)d_in[6], (const float*)d_in[7],
                         (const float*)d_in[8], (const float*)d_in[9]};
    float* out = (float*)d_out;

    __half *qh, *ql, *kh, *kl, *vh, *vl, *kh2, *kl2, *vh2, *vl2;
    __half *xa, *ea, *sa, *wh, *wl;
    cudaGetSymbolAddress((void**)&qh, g_qh);
    cudaGetSymbolAddress((void**)&ql, g_ql);
    cudaGetSymbolAddress((void**)&kh, g_kh);
    cudaGetSymbolAddress((void**)&kl, g_kl);
    cudaGetSymbolAddress((void**)&vh, g_vh);
    cudaGetSymbolAddress((void**)&vl, g_vl);
    cudaGetSymbolAddress((void**)&kh2, g_kh2);
    cudaGetSymbolAddress((void**)&kl2, g_kl2);
    cudaGetSymbolAddress((void**)&vh2, g_vh2);
    cudaGetSymbolAddress((void**)&vl2, g_vl2);
    cudaGetSymbolAddress((void**)&xa, g_xa);
    cudaGetSymbolAddress((void**)&ea, g_ea);
    cudaGetSymbolAddress((void**)&sa, g_sa);
    cudaGetSymbolAddress((void**)&wh, g_w6h);
    cudaGetSymbolAddress((void**)&wl, g_w6l);

    cudaFuncSetAttribute(gemm_qkv, cudaFuncAttributeMaxDynamicSharedMemorySize, GEMM_SMEM);
    cudaFuncSetAttribute(attn_mma, cudaFuncAttributeMaxDynamicSharedMemorySize, ATTN_SMEM);

    static cudaStream_t s1 = nullptr;
    static cudaEvent_t ev_fork = nullptr, ev_kv = nullptr;
    if (!s1) {
        cudaStreamCreateWithFlags(&s1, cudaStreamNonBlocking);
        cudaEventCreateWithFlags(&ev_fork, cudaEventDisableTiming);
        cudaEventCreateWithFlags(&ev_kv, cudaEventDisableTiming);
    }

    const size_t WSZ = (size_t)DMODEL * DMODEL;
    dim3 gg3(DMODEL / BN, MTOT / BM, 3);                 // (8, 32, 3)
    dim3 gg2(DMODEL / BN, MTOT / BM, 2);                 // cross K,V
    dim3 gg1(DMODEL / BN, MTOT / BM, 1);                 // cross Q
    dim3 ga(SEQ / 64, NHEAD, BATCH);                     // (16, 16, 4)

    // ---- splits ----
    SplitA Sa = {};
    Sa.src[0] = x;   Sa.dst[0] = xa;
    Sa.src[1] = enc; Sa.dst[1] = ea;
    split_a<<<dim3((MTOT * DMODEL) / (256 * 4), 2), 256>>>(Sa);

    SplitW Sw = {};
    for (int i = 0; i < 6; i++) {
        Sw.src[i] = w[i]; Sw.hi[i] = wh + i * WSZ; Sw.lo[i] = wl + i * WSZ;
    }
    split_w<<<dim3((int)(WSZ / (256 * 4)), 6), 256>>>(Sw);

    // ---- fork: s1 runs cross-K/V GEMM concurrently with self block ----
    cudaEventRecord(ev_fork, 0);
    cudaStreamWaitEvent(s1, ev_fork, 0);

    GemmTriple Pkv;
    Pkv.A[0] = ea; Pkv.A[1] = ea;
    Pkv.Bh[0] = wh + 4 * WSZ; Pkv.Bl[0] = wl + 4 * WSZ;
    Pkv.Bh[1] = wh + 5 * WSZ; Pkv.Bl[1] = wl + 5 * WSZ;
    Pkv.Ch[0] = kh2; Pkv.Cl[0] = kl2;
    Pkv.Ch[1] = vh2; Pkv.Cl[1] = vl2;
    gemm_qkv<<<gg2, GT, GEMM_SMEM, s1>>>(Pkv);
    cudaEventRecord(ev_kv, s1);

    // ---- self block (default stream) ----
    GemmTriple Ps;
    for (int zi = 0; zi < 3; zi++) {
        Ps.A[zi] = xa;
        Ps.Bh[zi] = wh + zi * WSZ; Ps.Bl[zi] = wl + zi * WSZ;
    }
    Ps.Ch[0] = qh; Ps.Cl[0] = ql;
    Ps.Ch[1] = kh; Ps.Cl[1] = kl;
    Ps.Ch[2] = vh; Ps.Cl[2] = vl;
    gemm_qkv<<<gg3, GT, GEMM_SMEM>>>(Ps);
    attn_mma<<<ga, 128, ATTN_SMEM>>>(qh, ql, kh, kl, vh, vl, nullptr, sa, 1);

    // ---- cross Q GEMM (A = attn_self output, fp16) ----
    GemmTriple Pq;
    Pq.A[0] = sa;
    Pq.Bh[0] = wh + 3 * WSZ; Pq.Bl[0] = wl + 3 * WSZ;
    Pq.Ch[0] = qh; Pq.Cl[0] = ql;
    gemm_qkv<<<gg1, GT, GEMM_SMEM>>>(Pq);

    // ---- join, then cross attention ----
    cudaStreamWaitEvent(0, ev_kv, 0);
    attn_mma<<<ga, 128, ATTN_SMEM>>>(qh, ql, kh2, kl2, vh2, vl2, out, nullptr, 0);
}